// round 1
// baseline (speedup 1.0000x reference)
#include <cuda_runtime.h>
#include <cuda_bf16.h>
#include <math.h>

// Problem constants
#define BB 2
#define SS 2048
#define EE 2048
#define HH 16
#define DD 128
#define MROWS (BB * SS)          // 4096
#define QKV_N (3 * EE)           // 6144

// ---------------- scratch (device globals: allocation-free) ----------------
__device__ float g_qkv[(size_t)MROWS * QKV_N];          // [4096, 6144]
__device__ float g_Qt[(size_t)BB * HH * DD * SS];       // [b,h,d,s]
__device__ float g_Kt[(size_t)BB * HH * DD * SS];       // [b,h,d,s]
__device__ float g_V [(size_t)BB * HH * SS * DD];       // [b,h,s,d]
__device__ float g_y [(size_t)MROWS * EE];              // [b,s,h,d] flat

// ---------------- GEMM: C[M,N] = A[M,K] @ B[N,K]^T (both row-major, NT) ----
__global__ __launch_bounds__(256, 2)
void gemm_nt(const float* __restrict__ A, const float* __restrict__ B,
             float* __restrict__ C, int M, int N, int K) {
    __shared__ float As[32][132];
    __shared__ float Bs[32][132];
    const int t  = threadIdx.x;
    const int tx = t & 15;
    const int ty = t >> 4;
    const int m0 = blockIdx.y * 128;
    const int n0 = blockIdx.x * 128;

    float acc[8][8];
#pragma unroll
    for (int i = 0; i < 8; i++)
#pragma unroll
        for (int j = 0; j < 8; j++) acc[i][j] = 0.f;

    const int lrow = t >> 3;        // 0..31
    const int lc4  = (t & 7) * 4;   // 0,4,...,28

    for (int k0 = 0; k0 < K; k0 += 32) {
        __syncthreads();
#pragma unroll
        for (int p = 0; p < 4; p++) {
            int row = lrow + p * 32;
            float4 a = *(const float4*)&A[(size_t)(m0 + row) * K + k0 + lc4];
            As[lc4 + 0][row] = a.x;
            As[lc4 + 1][row] = a.y;
            As[lc4 + 2][row] = a.z;
            As[lc4 + 3][row] = a.w;
            float4 b = *(const float4*)&B[(size_t)(n0 + row) * K + k0 + lc4];
            Bs[lc4 + 0][row] = b.x;
            Bs[lc4 + 1][row] = b.y;
            Bs[lc4 + 2][row] = b.z;
            Bs[lc4 + 3][row] = b.w;
        }
        __syncthreads();
#pragma unroll
        for (int kk = 0; kk < 32; kk++) {
            float a[8], bb[8];
            *(float4*)&a[0]  = *(const float4*)&As[kk][ty * 8];
            *(float4*)&a[4]  = *(const float4*)&As[kk][ty * 8 + 4];
            *(float4*)&bb[0] = *(const float4*)&Bs[kk][tx * 8];
            *(float4*)&bb[4] = *(const float4*)&Bs[kk][tx * 8 + 4];
#pragma unroll
            for (int i = 0; i < 8; i++)
#pragma unroll
                for (int j = 0; j < 8; j++)
                    acc[i][j] += a[i] * bb[j];
        }
    }

#pragma unroll
    for (int i = 0; i < 8; i++) {
        float* cp = &C[(size_t)(m0 + ty * 8 + i) * N + n0 + tx * 8];
        *(float4*)cp       = make_float4(acc[i][0], acc[i][1], acc[i][2], acc[i][3]);
        *(float4*)(cp + 4) = make_float4(acc[i][4], acc[i][5], acc[i][6], acc[i][7]);
    }
}

// ---------------- RoPE + head-transpose for Q,K → [b,h,d,s] ----------------
// idx layout: ((b*16+h)*128 + d)*2048 + s  (so writes are fully coalesced)
__global__ void rope_qk(const float* __restrict__ qkv,
                        float* __restrict__ Qt, float* __restrict__ Kt) {
    int idx = blockIdx.x * blockDim.x + threadIdx.x;
    int s  = idx & 2047;
    int d  = (idx >> 11) & 127;
    int bh = idx >> 18;
    int i  = d & 63;
    // inv_freq = 10000^(-i/64) = 2^(-(log2(1e4)/64) * i)
    float theta = (float)s * exp2f(-0.20762050593045998f * (float)i);
    float sn, cs;
    sincosf(theta, &sn, &cs);
    const float* row = qkv + (size_t)((bh >> 4) * 2048 + s) * QKV_N;
    int nq = (bh & 15) * 128;
    float qv = row[nq + d];
    float qp = row[nq + (d ^ 64)];
    float kv = row[2048 + nq + d];
    float kp = row[2048 + nq + (d ^ 64)];
    float qr = (d < 64) ? -qp : qp;
    float kr = (d < 64) ? -kp : kp;
    Qt[idx] = qv * cs + qr * sn;
    Kt[idx] = kv * cs + kr * sn;
}

// ---------------- V gather → [b,h,s,d] (float4 both sides) -----------------
__global__ void copy_v(const float* __restrict__ qkv, float* __restrict__ V) {
    int idx = (blockIdx.x * blockDim.x + threadIdx.x) * 4;
    int d  = idx & 127;
    int s  = (idx >> 7) & 2047;
    int bh = idx >> 18;
    *(float4*)&V[idx] =
        *(const float4*)&qkv[(size_t)((bh >> 4) * 2048 + s) * QKV_N + 4096 + (bh & 15) * 128 + d];
}

// ---------------- Flash attention: 64x64 tiles, fp32 -----------------------
// Qs/Ks: [128][68] (d-major, from Qt/Kt), Ps: [64][68] (kcol-major), Vs: [64][128]
#define APITCH 68
#define ATTN_SMEM ((2 * 128 * APITCH + 64 * APITCH + 64 * 128) * 4)

__global__ __launch_bounds__(256, 1)
void attn_kernel(const float* __restrict__ Qt, const float* __restrict__ Kt,
                 const float* __restrict__ Vg_, float* __restrict__ Y) {
    extern __shared__ float sm[];
    float* Qs = sm;                        // [128][68]
    float* Ks = sm + 128 * APITCH;         // [128][68]
    float* Ps = sm + 2 * 128 * APITCH;     // [64][68]
    float* Vs = Ps + 64 * APITCH;          // [64][128]

    const int t  = threadIdx.x;
    const int tx = t & 15;
    const int ty = t >> 4;
    const int qb = blockIdx.x;
    const int h  = blockIdx.y;
    const int b  = blockIdx.z;
    const int q0 = qb * 64;

    const size_t bh = (size_t)(b * HH + h);
    const float* Qg = Qt  + bh * DD * SS;  // [d][s]
    const float* Kg = Kt  + bh * DD * SS;  // [d][s]
    const float* Vg = Vg_ + bh * SS * DD;  // [s][d]

    // load Q tile, fold in softmax scale 1/sqrt(128)
    {
        const float scale = 0.088388347648318447f;
        int d = t >> 4;
        int c = (t & 15) * 4;
#pragma unroll
        for (int p = 0; p < 8; p++, d += 16) {
            float4 v = *(const float4*)&Qg[d * SS + q0 + c];
            v.x *= scale; v.y *= scale; v.z *= scale; v.w *= scale;
            *(float4*)&Qs[d * APITCH + c] = v;
        }
    }

    float o[4][8];
#pragma unroll
    for (int i = 0; i < 4; i++)
#pragma unroll
        for (int j = 0; j < 8; j++) o[i][j] = 0.f;
    float mrow[4] = {-1e30f, -1e30f, -1e30f, -1e30f};
    float lrow[4] = {0.f, 0.f, 0.f, 0.f};

    for (int kt = 0; kt <= qb; kt++) {
        const int k0 = kt * 64;
        __syncthreads();   // protect SMEM reuse (also covers initial Q load)
        {
            int d = t >> 4;
            int c = (t & 15) * 4;
#pragma unroll
            for (int p = 0; p < 8; p++, d += 16)
                *(float4*)&Ks[d * APITCH + c] = *(const float4*)&Kg[d * SS + k0 + c];
        }
        {
            int lane = t & 31;
            int r    = t >> 5;
#pragma unroll
            for (int p = 0; p < 8; p++) {
                int kc = r + p * 8;
                *(float4*)&Vs[kc * 128 + lane * 4] =
                    *(const float4*)&Vg[(size_t)(k0 + kc) * 128 + lane * 4];
            }
        }
        __syncthreads();

        // scores S = Q^T K (contract over d)
        float s[4][4];
#pragma unroll
        for (int i = 0; i < 4; i++)
#pragma unroll
            for (int j = 0; j < 4; j++) s[i][j] = 0.f;

#pragma unroll 4
        for (int kk = 0; kk < 128; kk++) {
            float4 qv = *(const float4*)&Qs[kk * APITCH + ty * 4];
            float4 kv = *(const float4*)&Ks[kk * APITCH + tx * 4];
            float qa[4] = {qv.x, qv.y, qv.z, qv.w};
            float ka[4] = {kv.x, kv.y, kv.z, kv.w};
#pragma unroll
            for (int i = 0; i < 4; i++)
#pragma unroll
                for (int j = 0; j < 4; j++)
                    s[i][j] += qa[i] * ka[j];
        }

        if (kt == qb) {   // only diagonal tile needs masking
#pragma unroll
            for (int i = 0; i < 4; i++) {
                int row = q0 + ty * 4 + i;
#pragma unroll
                for (int j = 0; j < 4; j++) {
                    int col = k0 + tx * 4 + j;
                    if (col > row) s[i][j] = -1e30f;
                }
            }
        }

        // online softmax (rows owned by the 16 lanes sharing ty)
#pragma unroll
        for (int i = 0; i < 4; i++) {
            float tm = fmaxf(fmaxf(s[i][0], s[i][1]), fmaxf(s[i][2], s[i][3]));
#pragma unroll
            for (int off = 8; off > 0; off >>= 1)
                tm = fmaxf(tm, __shfl_xor_sync(0xffffffffu, tm, off));
            float mnew  = fmaxf(mrow[i], tm);
            float alpha = __expf(mrow[i] - mnew);
            mrow[i] = mnew;
            float rs = 0.f;
#pragma unroll
            for (int j = 0; j < 4; j++) {
                float p = __expf(s[i][j] - mnew);
                s[i][j] = p;
                rs += p;
            }
#pragma unroll
            for (int off = 8; off > 0; off >>= 1)
                rs += __shfl_xor_sync(0xffffffffu, rs, off);
            lrow[i] = lrow[i] * alpha + rs;
#pragma unroll
            for (int j = 0; j < 8; j++) o[i][j] *= alpha;
        }

        // stage P transposed: Ps[kcol][qrow]
#pragma unroll
        for (int j = 0; j < 4; j++)
#pragma unroll
            for (int i = 0; i < 4; i++)
                Ps[(tx * 4 + j) * APITCH + ty * 4 + i] = s[i][j];
        __syncthreads();

        // O += P @ V
#pragma unroll 2
        for (int kc = 0; kc < 64; kc++) {
            float4 pv = *(const float4*)&Ps[kc * APITCH + ty * 4];
            float4 v0 = *(const float4*)&Vs[kc * 128 + tx * 8];
            float4 v1 = *(const float4*)&Vs[kc * 128 + tx * 8 + 4];
            float pa[4] = {pv.x, pv.y, pv.z, pv.w};
            float va[8] = {v0.x, v0.y, v0.z, v0.w, v1.x, v1.y, v1.z, v1.w};
#pragma unroll
            for (int i = 0; i < 4; i++)
#pragma unroll
                for (int j = 0; j < 8; j++)
                    o[i][j] += pa[i] * va[j];
        }
    }

    // normalize + write Y in [b, s, h, d] (flat [4096, 2048])
#pragma unroll
    for (int i = 0; i < 4; i++) {
        float inv = 1.f / lrow[i];
        int row = q0 + ty * 4 + i;
        float* yp = &Y[(((size_t)b * SS + row) * HH + h) * DD + tx * 8];
        *(float4*)yp       = make_float4(o[i][0] * inv, o[i][1] * inv, o[i][2] * inv, o[i][3] * inv);
        *(float4*)(yp + 4) = make_float4(o[i][4] * inv, o[i][5] * inv, o[i][6] * inv, o[i][7] * inv);
    }
}

// ---------------- launch -----------------------------------------------------
extern "C" void kernel_launch(void* const* d_in, const int* in_sizes, int n_in,
                              void* d_out, int out_size) {
    const float* x     = (const float*)d_in[0];
    const float* w_qkv = (const float*)d_in[1];
    const float* w_out = (const float*)d_in[2];
    float* out = (float*)d_out;

    float *p_qkv, *p_Qt, *p_Kt, *p_V, *p_y;
    cudaGetSymbolAddress((void**)&p_qkv, g_qkv);
    cudaGetSymbolAddress((void**)&p_Qt,  g_Qt);
    cudaGetSymbolAddress((void**)&p_Kt,  g_Kt);
    cudaGetSymbolAddress((void**)&p_V,   g_V);
    cudaGetSymbolAddress((void**)&p_y,   g_y);

    cudaFuncSetAttribute(attn_kernel, cudaFuncAttributeMaxDynamicSharedMemorySize, ATTN_SMEM);

    // 1) qkv = x @ w_qkv^T
    gemm_nt<<<dim3(QKV_N / 128, MROWS / 128), 256>>>(x, w_qkv, p_qkv, MROWS, QKV_N, EE);
    // 2) RoPE + transpose Q,K ; gather V
    rope_qk<<<(BB * HH * DD * SS) / 256, 256>>>(p_qkv, p_Qt, p_Kt);
    copy_v<<<(BB * HH * SS * DD) / 1024, 256>>>(p_qkv, p_V);
    // 3) flash attention
    attn_kernel<<<dim3(SS / 64, HH, BB), 256, ATTN_SMEM>>>(p_Qt, p_Kt, p_V, p_y);
    // 4) out = y @ w_out^T
    gemm_nt<<<dim3(EE / 128, MROWS / 128), 256>>>(p_y, w_out, out, MROWS, EE, EE);
}

// round 3
// speedup vs baseline: 1.8743x; 1.8743x over previous
#include <cuda_runtime.h>
#include <cuda_bf16.h>
#include <cstdint>
#include <math.h>

// Problem constants
#define BB 2
#define SS 2048
#define EE 2048
#define HH 16
#define DD 128
#define MROWS (BB * SS)          // 4096
#define QKV_N (3 * EE)           // 6144

// ---------------- scratch (device globals: allocation-free) ----------------
__device__ float g_x   [(size_t)MROWS * EE];            // tf32-rounded x
__device__ float g_wqkv[(size_t)QKV_N * EE];            // tf32-rounded w_qkv
__device__ float g_wout[(size_t)EE * EE];               // tf32-rounded w_out
__device__ float g_qkv [(size_t)MROWS * QKV_N];         // [4096, 6144] fp32
__device__ float g_Qt  [(size_t)BB * HH * DD * SS];     // [b,h,d,s]
__device__ float g_Kt  [(size_t)BB * HH * DD * SS];     // [b,h,d,s]
__device__ float g_V   [(size_t)BB * HH * SS * DD];     // [b,h,s,d]
__device__ float g_y   [(size_t)MROWS * EE];            // [b,s,h,d], tf32-rounded

// ======================= helpers ===========================================
__device__ __forceinline__ uint32_t smem_u32(const void* p) {
    uint32_t a;
    asm("{ .reg .u64 t; cvta.to.shared.u64 t, %1; cvt.u32.u64 %0, t; }"
        : "=r"(a) : "l"(p));
    return a;
}

__device__ __forceinline__ float to_tf32(float x) {
    uint32_t u;
    asm("cvt.rna.tf32.f32 %0, %1;" : "=r"(u) : "f"(x));
    return __uint_as_float(u);
}

#define CPA16(dst, src) \
    asm volatile("cp.async.cg.shared.global [%0], [%1], 16;" :: "r"(dst), "l"(src))
#define CPA_COMMIT()  asm volatile("cp.async.commit_group;" ::: "memory")
#define CPA_WAIT1()   asm volatile("cp.async.wait_group 1;" ::: "memory")

#define LDSM4(r, addr)                                                        \
    asm volatile("ldmatrix.sync.aligned.m8n8.x4.shared.b16 {%0,%1,%2,%3}, [%4];" \
        : "=r"((r)[0]), "=r"((r)[1]), "=r"((r)[2]), "=r"((r)[3]) : "r"(addr))

#define MMA_TF32(c, a, b0, b1)                                                \
    asm volatile("mma.sync.aligned.m16n8k8.row.col.f32.tf32.tf32.f32 "        \
        "{%0,%1,%2,%3}, {%4,%5,%6,%7}, {%8,%9}, {%0,%1,%2,%3};"               \
        : "+f"((c)[0]), "+f"((c)[1]), "+f"((c)[2]), "+f"((c)[3])              \
        : "r"((a)[0]), "r"((a)[1]), "r"((a)[2]), "r"((a)[3]), "r"(b0), "r"(b1))

// ================== mma.sync tf32 GEMM: C[M,N] = A[M,K] @ B[N,K]^T =========
// CTA 128x128, 8 warps (2m x 4n), warptile 64x32, K-chunk 32, 3-stage cp.async
#define GP 36                               // SMEM pitch in floats (pitch%32==4)
#define BOFF (128 * GP * 4)                 // B offset within a stage (bytes)
#define STG_B (2 * 128 * GP * 4)            // stage bytes = 36864
#define GEMM_SMEM (3 * STG_B)               // 110592

__device__ __forceinline__ void g2s_stage(const float* A, const float* B, int K,
                                          uint32_t stg, int tid) {
#pragma unroll
    for (int j = 0; j < 4; j++) {
        int cid = tid + j * 256;
        int row = cid >> 3, chk = cid & 7;
        CPA16(stg + (uint32_t)(row * GP + chk * 4) * 4,
              A + (size_t)row * K + chk * 4);
    }
#pragma unroll
    for (int j = 0; j < 4; j++) {
        int cid = tid + j * 256;
        int row = cid >> 3, chk = cid & 7;
        CPA16(stg + BOFF + (uint32_t)(row * GP + chk * 4) * 4,
              B + (size_t)row * K + chk * 4);
    }
}

__global__ __launch_bounds__(256, 1)
void gemm_mma(const float* __restrict__ A, const float* __restrict__ B,
              float* __restrict__ C, int N, int K) {
    extern __shared__ char smem[];
    const uint32_t sbase = smem_u32(smem);
    const int tid  = threadIdx.x;
    const int wid  = tid >> 5;
    const int lane = tid & 31;
    const int wm   = wid >> 2;              // 0..1  (64 rows each)
    const int wn   = wid & 3;               // 0..3  (32 cols each)
    const int m0 = blockIdx.y * 128;
    const int n0 = blockIdx.x * 128;
    const int iters = K >> 5;

    const float* Ab = A + (size_t)m0 * K;
    const float* Bb = B + (size_t)n0 * K;

    float c[4][4][4];
#pragma unroll
    for (int i = 0; i < 4; i++)
#pragma unroll
        for (int j = 0; j < 4; j++)
#pragma unroll
            for (int q = 0; q < 4; q++) c[i][j][q] = 0.f;

    // ldmatrix per-thread base addresses
    const int sub = lane >> 3;              // 0..3
    const int r8  = lane & 7;
    const uint32_t aoff = (uint32_t)((wm * 64 + (sub & 1) * 8 + r8) * GP + (sub >> 1) * 4) * 4;
    const uint32_t boff = BOFF + (uint32_t)((wn * 32 + (sub >> 1) * 8 + r8) * GP + (sub & 1) * 4) * 4;

    // prologue: stages 0,1
    g2s_stage(Ab, Bb, K, sbase, tid);            CPA_COMMIT();
    g2s_stage(Ab + 32, Bb + 32, K, sbase + STG_B, tid); CPA_COMMIT();

    for (int i = 0; i < iters; i++) {
        CPA_WAIT1();
        __syncthreads();
        if (i + 2 < iters) {
            uint32_t stg = sbase + (uint32_t)((i + 2) % 3) * STG_B;
            g2s_stage(Ab + (i + 2) * 32, Bb + (i + 2) * 32, K, stg, tid);
            CPA_COMMIT();
        }
        const uint32_t stg = sbase + (uint32_t)(i % 3) * STG_B;
        const uint32_t ab = stg + aoff;
        const uint32_t bb = stg + boff;
#pragma unroll
        for (int kk = 0; kk < 32; kk += 8) {
            uint32_t a[4][4], b[2][4];
#pragma unroll
            for (int im = 0; im < 4; im++)
                LDSM4(a[im], ab + (uint32_t)(im * 16 * GP + kk) * 4);
#pragma unroll
            for (int p = 0; p < 2; p++)
                LDSM4(b[p], bb + (uint32_t)(p * 16 * GP + kk) * 4);
#pragma unroll
            for (int im = 0; im < 4; im++)
#pragma unroll
                for (int jn = 0; jn < 4; jn++)
                    MMA_TF32(c[im][jn], a[im],
                             b[jn >> 1][(jn & 1) * 2], b[jn >> 1][(jn & 1) * 2 + 1]);
        }
    }

    // epilogue
    const int g = lane >> 2, q = lane & 3;
#pragma unroll
    for (int im = 0; im < 4; im++)
#pragma unroll
        for (int jn = 0; jn < 4; jn++) {
            int row = m0 + wm * 64 + im * 16 + g;
            int col = n0 + wn * 32 + jn * 8 + q * 2;
            *(float2*)&C[(size_t)row * N + col]       = make_float2(c[im][jn][0], c[im][jn][1]);
            *(float2*)&C[(size_t)(row + 8) * N + col] = make_float2(c[im][jn][2], c[im][jn][3]);
        }
}

// ---------------- tf32 round-to-nearest copy -------------------------------
__global__ void round_tf32_k(const float4* __restrict__ in, float4* __restrict__ out, int n4) {
    int i = blockIdx.x * blockDim.x + threadIdx.x;
    if (i >= n4) return;
    float4 v = in[i];
    v.x = to_tf32(v.x); v.y = to_tf32(v.y);
    v.z = to_tf32(v.z); v.w = to_tf32(v.w);
    out[i] = v;
}

// ---------------- RoPE + head-transpose for Q,K → [b,h,d,s] ----------------
__global__ void rope_qk(const float* __restrict__ qkv,
                        float* __restrict__ Qt, float* __restrict__ Kt) {
    int idx = blockIdx.x * blockDim.x + threadIdx.x;
    int s  = idx & 2047;
    int d  = (idx >> 11) & 127;
    int bh = idx >> 18;
    int i  = d & 63;
    float theta = (float)s * exp2f(-0.20762050593045998f * (float)i);
    float sn, cs;
    sincosf(theta, &sn, &cs);
    const float* row = qkv + (size_t)((bh >> 4) * 2048 + s) * QKV_N;
    int nq = (bh & 15) * 128;
    float qv = row[nq + d];
    float qp = row[nq + (d ^ 64)];
    float kv = row[2048 + nq + d];
    float kp = row[2048 + nq + (d ^ 64)];
    float qr = (d < 64) ? -qp : qp;
    float kr = (d < 64) ? -kp : kp;
    Qt[idx] = qv * cs + qr * sn;
    Kt[idx] = kv * cs + kr * sn;
}

// ---------------- V gather → [b,h,s,d] --------------------------------------
__global__ void copy_v(const float* __restrict__ qkv, float* __restrict__ V) {
    int idx = (blockIdx.x * blockDim.x + threadIdx.x) * 4;
    int d  = idx & 127;
    int s  = (idx >> 7) & 2047;
    int bh = idx >> 18;
    *(float4*)&V[idx] =
        *(const float4*)&qkv[(size_t)((bh >> 4) * 2048 + s) * QKV_N + 4096 + (bh & 15) * 128 + d];
}

// ---------------- Flash attention: 64x64 tiles, fp32 -----------------------
#define APITCH 68
#define ATTN_SMEM ((2 * 128 * APITCH + 64 * APITCH + 64 * 128) * 4)

__global__ __launch_bounds__(256, 1)
void attn_kernel(const float* __restrict__ Qt, const float* __restrict__ Kt,
                 const float* __restrict__ Vg_, float* __restrict__ Y) {
    extern __shared__ float sm[];
    float* Qs = sm;                        // [128][68]
    float* Ks = sm + 128 * APITCH;         // [128][68]
    float* Ps = sm + 2 * 128 * APITCH;     // [64][68]
    float* Vs = Ps + 64 * APITCH;          // [64][128]

    const int t  = threadIdx.x;
    const int tx = t & 15;
    const int ty = t >> 4;
    const int qb = blockIdx.x;
    const int h  = blockIdx.y;
    const int b  = blockIdx.z;
    const int q0 = qb * 64;

    const size_t bh = (size_t)(b * HH + h);
    const float* Qg = Qt  + bh * DD * SS;
    const float* Kg = Kt  + bh * DD * SS;
    const float* Vg = Vg_ + bh * SS * DD;

    {
        const float scale = 0.088388347648318447f;
        int d = t >> 4;
        int c = (t & 15) * 4;
#pragma unroll
        for (int p = 0; p < 8; p++, d += 16) {
            float4 v = *(const float4*)&Qg[d * SS + q0 + c];
            v.x *= scale; v.y *= scale; v.z *= scale; v.w *= scale;
            *(float4*)&Qs[d * APITCH + c] = v;
        }
    }

    float o[4][8];
#pragma unroll
    for (int i = 0; i < 4; i++)
#pragma unroll
        for (int j = 0; j < 8; j++) o[i][j] = 0.f;
    float mrow[4] = {-1e30f, -1e30f, -1e30f, -1e30f};
    float lrow[4] = {0.f, 0.f, 0.f, 0.f};

    for (int kt = 0; kt <= qb; kt++) {
        const int k0 = kt * 64;
        __syncthreads();
        {
            int d = t >> 4;
            int c = (t & 15) * 4;
#pragma unroll
            for (int p = 0; p < 8; p++, d += 16)
                *(float4*)&Ks[d * APITCH + c] = *(const float4*)&Kg[d * SS + k0 + c];
        }
        {
            int lane = t & 31;
            int r    = t >> 5;
#pragma unroll
            for (int p = 0; p < 8; p++) {
                int kc = r + p * 8;
                *(float4*)&Vs[kc * 128 + lane * 4] =
                    *(const float4*)&Vg[(size_t)(k0 + kc) * 128 + lane * 4];
            }
        }
        __syncthreads();

        float s[4][4];
#pragma unroll
        for (int i = 0; i < 4; i++)
#pragma unroll
            for (int j = 0; j < 4; j++) s[i][j] = 0.f;

#pragma unroll 4
        for (int kk = 0; kk < 128; kk++) {
            float4 qv = *(const float4*)&Qs[kk * APITCH + ty * 4];
            float4 kv = *(const float4*)&Ks[kk * APITCH + tx * 4];
            float qa[4] = {qv.x, qv.y, qv.z, qv.w};
            float ka[4] = {kv.x, kv.y, kv.z, kv.w};
#pragma unroll
            for (int i = 0; i < 4; i++)
#pragma unroll
                for (int j = 0; j < 4; j++)
                    s[i][j] += qa[i] * ka[j];
        }

        if (kt == qb) {
#pragma unroll
            for (int i = 0; i < 4; i++) {
                int row = q0 + ty * 4 + i;
#pragma unroll
                for (int j = 0; j < 4; j++) {
                    int col = k0 + tx * 4 + j;
                    if (col > row) s[i][j] = -1e30f;
                }
            }
        }

#pragma unroll
        for (int i = 0; i < 4; i++) {
            float tm = fmaxf(fmaxf(s[i][0], s[i][1]), fmaxf(s[i][2], s[i][3]));
#pragma unroll
            for (int off = 8; off > 0; off >>= 1)
                tm = fmaxf(tm, __shfl_xor_sync(0xffffffffu, tm, off));
            float mnew  = fmaxf(mrow[i], tm);
            float alpha = __expf(mrow[i] - mnew);
            mrow[i] = mnew;
            float rs = 0.f;
#pragma unroll
            for (int j = 0; j < 4; j++) {
                float p = __expf(s[i][j] - mnew);
                s[i][j] = p;
                rs += p;
            }
#pragma unroll
            for (int off = 8; off > 0; off >>= 1)
                rs += __shfl_xor_sync(0xffffffffu, rs, off);
            lrow[i] = lrow[i] * alpha + rs;
#pragma unroll
            for (int j = 0; j < 8; j++) o[i][j] *= alpha;
        }

#pragma unroll
        for (int j = 0; j < 4; j++)
#pragma unroll
            for (int i = 0; i < 4; i++)
                Ps[(tx * 4 + j) * APITCH + ty * 4 + i] = s[i][j];
        __syncthreads();

#pragma unroll 2
        for (int kc = 0; kc < 64; kc++) {
            float4 pv = *(const float4*)&Ps[kc * APITCH + ty * 4];
            float4 v0 = *(const float4*)&Vs[kc * 128 + tx * 8];
            float4 v1 = *(const float4*)&Vs[kc * 128 + tx * 8 + 4];
            float pa[4] = {pv.x, pv.y, pv.z, pv.w};
            float va[8] = {v0.x, v0.y, v0.z, v0.w, v1.x, v1.y, v1.z, v1.w};
#pragma unroll
            for (int i = 0; i < 4; i++)
#pragma unroll
                for (int j = 0; j < 8; j++)
                    o[i][j] += pa[i] * va[j];
        }
    }

    // normalize + tf32-round + write Y in [b, s, h, d]
#pragma unroll
    for (int i = 0; i < 4; i++) {
        float inv = 1.f / lrow[i];
        int row = q0 + ty * 4 + i;
        float* yp = &Y[(((size_t)b * SS + row) * HH + h) * DD + tx * 8];
        *(float4*)yp = make_float4(
            to_tf32(o[i][0] * inv), to_tf32(o[i][1] * inv),
            to_tf32(o[i][2] * inv), to_tf32(o[i][3] * inv));
        *(float4*)(yp + 4) = make_float4(
            to_tf32(o[i][4] * inv), to_tf32(o[i][5] * inv),
            to_tf32(o[i][6] * inv), to_tf32(o[i][7] * inv));
    }
}

// ---------------- launch -----------------------------------------------------
extern "C" void kernel_launch(void* const* d_in, const int* in_sizes, int n_in,
                              void* d_out, int out_size) {
    const float* x     = (const float*)d_in[0];
    const float* w_qkv = (const float*)d_in[1];
    const float* w_out = (const float*)d_in[2];
    float* out = (float*)d_out;

    float *p_x, *p_wqkv, *p_wout, *p_qkv, *p_Qt, *p_Kt, *p_V, *p_y;
    cudaGetSymbolAddress((void**)&p_x,    g_x);
    cudaGetSymbolAddress((void**)&p_wqkv, g_wqkv);
    cudaGetSymbolAddress((void**)&p_wout, g_wout);
    cudaGetSymbolAddress((void**)&p_qkv,  g_qkv);
    cudaGetSymbolAddress((void**)&p_Qt,   g_Qt);
    cudaGetSymbolAddress((void**)&p_Kt,   g_Kt);
    cudaGetSymbolAddress((void**)&p_V,    g_V);
    cudaGetSymbolAddress((void**)&p_y,    g_y);

    cudaFuncSetAttribute(gemm_mma, cudaFuncAttributeMaxDynamicSharedMemorySize, GEMM_SMEM);
    cudaFuncSetAttribute(attn_kernel, cudaFuncAttributeMaxDynamicSharedMemorySize, ATTN_SMEM);

    // 0) round GEMM operands to tf32 (RNA)
    round_tf32_k<<<(MROWS * EE / 4 + 255) / 256, 256>>>((const float4*)x, (float4*)p_x, MROWS * EE / 4);
    round_tf32_k<<<(QKV_N * EE / 4 + 255) / 256, 256>>>((const float4*)w_qkv, (float4*)p_wqkv, QKV_N * EE / 4);
    round_tf32_k<<<(EE * EE / 4 + 255) / 256, 256>>>((const float4*)w_out, (float4*)p_wout, EE * EE / 4);

    // 1) qkv = x @ w_qkv^T  (mma.sync tf32)
    gemm_mma<<<dim3(QKV_N / 128, MROWS / 128), 256, GEMM_SMEM>>>(p_x, p_wqkv, p_qkv, QKV_N, EE);
    // 2) RoPE + transpose Q,K ; gather V
    rope_qk<<<(BB * HH * DD * SS) / 256, 256>>>(p_qkv, p_Qt, p_Kt);
    copy_v<<<(BB * HH * SS * DD) / 1024, 256>>>(p_qkv, p_V);
    // 3) flash attention (fp32)
    attn_kernel<<<dim3(SS / 64, HH, BB), 256, ATTN_SMEM>>>(p_Qt, p_Kt, p_V, p_y);
    // 4) out = y @ w_out^T  (mma.sync tf32)
    gemm_mma<<<dim3(EE / 128, MROWS / 128), 256, GEMM_SMEM>>>(p_y, p_wout, out, EE, EE);
}

// round 4
// speedup vs baseline: 3.3333x; 1.7784x over previous
#include <cuda_runtime.h>
#include <cuda_bf16.h>
#include <cstdint>
#include <math.h>

// Problem constants
#define BB 2
#define SS 2048
#define EE 2048
#define HH 16
#define DD 128
#define MROWS (BB * SS)          // 4096
#define QKV_N (3 * EE)           // 6144

// ---------------- scratch (device globals: allocation-free) ----------------
__device__ float g_x   [(size_t)MROWS * EE];            // tf32-rounded x
__device__ float g_wqkv[(size_t)QKV_N * EE];            // tf32-rounded w_qkv
__device__ float g_wout[(size_t)EE * EE];               // tf32-rounded w_out
__device__ float g_qkv [(size_t)MROWS * QKV_N];         // [4096, 6144] fp32
__device__ float g_Q   [(size_t)BB * HH * SS * DD];     // [b,h,s,d] (roped)
__device__ float g_K   [(size_t)BB * HH * SS * DD];     // [b,h,s,d] (roped)
__device__ float g_Vt  [(size_t)BB * HH * DD * SS];     // [b,h,d,s]
__device__ float g_y   [(size_t)MROWS * EE];            // [b,s,h,d], tf32-rounded

// ======================= helpers ===========================================
__device__ __forceinline__ uint32_t smem_u32(const void* p) {
    uint32_t a;
    asm("{ .reg .u64 t; cvta.to.shared.u64 t, %1; cvt.u32.u64 %0, t; }"
        : "=r"(a) : "l"(p));
    return a;
}

__device__ __forceinline__ float to_tf32(float x) {
    uint32_t u;
    asm("cvt.rna.tf32.f32 %0, %1;" : "=r"(u) : "f"(x));
    return __uint_as_float(u);
}

__device__ __forceinline__ float4 round4(float4 v) {
    v.x = to_tf32(v.x); v.y = to_tf32(v.y);
    v.z = to_tf32(v.z); v.w = to_tf32(v.w);
    return v;
}

#define CPA16(dst, src) \
    asm volatile("cp.async.cg.shared.global [%0], [%1], 16;" :: "r"(dst), "l"(src))
#define CPA_COMMIT()  asm volatile("cp.async.commit_group;" ::: "memory")
#define CPA_WAIT1()   asm volatile("cp.async.wait_group 1;" ::: "memory")

#define LDSM4(r, addr)                                                        \
    asm volatile("ldmatrix.sync.aligned.m8n8.x4.shared.b16 {%0,%1,%2,%3}, [%4];" \
        : "=r"((r)[0]), "=r"((r)[1]), "=r"((r)[2]), "=r"((r)[3]) : "r"(addr))

#define MMA_TF32(c, a, b0, b1)                                                \
    asm volatile("mma.sync.aligned.m16n8k8.row.col.f32.tf32.tf32.f32 "        \
        "{%0,%1,%2,%3}, {%4,%5,%6,%7}, {%8,%9}, {%0,%1,%2,%3};"               \
        : "+f"((c)[0]), "+f"((c)[1]), "+f"((c)[2]), "+f"((c)[3])              \
        : "r"((a)[0]), "r"((a)[1]), "r"((a)[2]), "r"((a)[3]), "r"(b0), "r"(b1))

// ================== mma.sync tf32 GEMM: C[M,N] = A[M,K] @ B[N,K]^T =========
#define GP 36
#define BOFF (128 * GP * 4)
#define STG_B (2 * 128 * GP * 4)
#define GEMM_SMEM (3 * STG_B)

__device__ __forceinline__ void g2s_stage(const float* A, const float* B, int K,
                                          uint32_t stg, int tid) {
#pragma unroll
    for (int j = 0; j < 4; j++) {
        int cid = tid + j * 256;
        int row = cid >> 3, chk = cid & 7;
        CPA16(stg + (uint32_t)(row * GP + chk * 4) * 4,
              A + (size_t)row * K + chk * 4);
    }
#pragma unroll
    for (int j = 0; j < 4; j++) {
        int cid = tid + j * 256;
        int row = cid >> 3, chk = cid & 7;
        CPA16(stg + BOFF + (uint32_t)(row * GP + chk * 4) * 4,
              B + (size_t)row * K + chk * 4);
    }
}

__global__ __launch_bounds__(256, 1)
void gemm_mma(const float* __restrict__ A, const float* __restrict__ B,
              float* __restrict__ C, int N, int K) {
    extern __shared__ char smem[];
    const uint32_t sbase = smem_u32(smem);
    const int tid  = threadIdx.x;
    const int wid  = tid >> 5;
    const int lane = tid & 31;
    const int wm   = wid >> 2;
    const int wn   = wid & 3;
    const int m0 = blockIdx.y * 128;
    const int n0 = blockIdx.x * 128;
    const int iters = K >> 5;

    const float* Ab = A + (size_t)m0 * K;
    const float* Bb = B + (size_t)n0 * K;

    float c[4][4][4];
#pragma unroll
    for (int i = 0; i < 4; i++)
#pragma unroll
        for (int j = 0; j < 4; j++)
#pragma unroll
            for (int q = 0; q < 4; q++) c[i][j][q] = 0.f;

    const int sub = lane >> 3;
    const int r8  = lane & 7;
    const uint32_t aoff = (uint32_t)((wm * 64 + (sub & 1) * 8 + r8) * GP + (sub >> 1) * 4) * 4;
    const uint32_t boff = BOFF + (uint32_t)((wn * 32 + (sub >> 1) * 8 + r8) * GP + (sub & 1) * 4) * 4;

    g2s_stage(Ab, Bb, K, sbase, tid);            CPA_COMMIT();
    g2s_stage(Ab + 32, Bb + 32, K, sbase + STG_B, tid); CPA_COMMIT();

    for (int i = 0; i < iters; i++) {
        CPA_WAIT1();
        __syncthreads();
        if (i + 2 < iters) {
            uint32_t stg = sbase + (uint32_t)((i + 2) % 3) * STG_B;
            g2s_stage(Ab + (i + 2) * 32, Bb + (i + 2) * 32, K, stg, tid);
            CPA_COMMIT();
        }
        const uint32_t stg = sbase + (uint32_t)(i % 3) * STG_B;
        const uint32_t ab = stg + aoff;
        const uint32_t bb = stg + boff;
#pragma unroll
        for (int kk = 0; kk < 32; kk += 8) {
            uint32_t a[4][4], b[2][4];
#pragma unroll
            for (int im = 0; im < 4; im++)
                LDSM4(a[im], ab + (uint32_t)(im * 16 * GP + kk) * 4);
#pragma unroll
            for (int p = 0; p < 2; p++)
                LDSM4(b[p], bb + (uint32_t)(p * 16 * GP + kk) * 4);
#pragma unroll
            for (int im = 0; im < 4; im++)
#pragma unroll
                for (int jn = 0; jn < 4; jn++)
                    MMA_TF32(c[im][jn], a[im],
                             b[jn >> 1][(jn & 1) * 2], b[jn >> 1][(jn & 1) * 2 + 1]);
        }
    }

    const int g = lane >> 2, q = lane & 3;
#pragma unroll
    for (int im = 0; im < 4; im++)
#pragma unroll
        for (int jn = 0; jn < 4; jn++) {
            int row = m0 + wm * 64 + im * 16 + g;
            int col = n0 + wn * 32 + jn * 8 + q * 2;
            *(float2*)&C[(size_t)row * N + col]       = make_float2(c[im][jn][0], c[im][jn][1]);
            *(float2*)&C[(size_t)(row + 8) * N + col] = make_float2(c[im][jn][2], c[im][jn][3]);
        }
}

// ---------------- tf32 round-to-nearest copy -------------------------------
__global__ void round_tf32_k(const float4* __restrict__ in, float4* __restrict__ out, int n4) {
    int i = blockIdx.x * blockDim.x + threadIdx.x;
    if (i >= n4) return;
    out[i] = round4(in[i]);
}

// ---------------- RoPE for Q,K → [b,h,s,d] ---------------------------------
__global__ void rope_qk(const float* __restrict__ qkv,
                        float* __restrict__ Q, float* __restrict__ K) {
    int idx = blockIdx.x * blockDim.x + threadIdx.x;
    int d  = idx & 127;
    int s  = (idx >> 7) & 2047;
    int bh = idx >> 18;
    int i  = d & 63;
    float theta = (float)s * exp2f(-0.20762050593045998f * (float)i);
    float sn, cs;
    sincosf(theta, &sn, &cs);
    const float* row = qkv + (size_t)((bh >> 4) * 2048 + s) * QKV_N;
    int nq = (bh & 15) * 128;
    float qv = row[nq + d];
    float qp = row[nq + (d ^ 64)];
    float kv = row[2048 + nq + d];
    float kp = row[2048 + nq + (d ^ 64)];
    float qr = (d < 64) ? -qp : qp;
    float kr = (d < 64) ? -kp : kp;
    Q[idx] = qv * cs + qr * sn;
    K[idx] = kv * cs + kr * sn;
}

// ---------------- V transpose → [b,h,d,s] ----------------------------------
__global__ void transpose_v(const float* __restrict__ qkv, float* __restrict__ Vt) {
    __shared__ float t[32][33];
    int bh = blockIdx.z;
    int b = bh >> 4, h = bh & 15;
    int s0 = blockIdx.x * 32, d0 = blockIdx.y * 32;
    int tx = threadIdx.x, ty = threadIdx.y;
    const float* src = qkv + ((size_t)(b * SS + s0 + ty)) * QKV_N + 4096 + h * 128 + d0 + tx;
#pragma unroll
    for (int j = 0; j < 32; j += 8)
        t[ty + j][tx] = src[(size_t)j * QKV_N];
    __syncthreads();
    float* dst = Vt + ((size_t)bh * DD + d0 + ty) * SS + s0 + tx;
#pragma unroll
    for (int j = 0; j < 32; j += 8)
        dst[(size_t)j * SS] = t[tx][ty + j];
}

// ---------------- Flash attention via mma.sync tf32 ------------------------
// CTA: 128 q-rows; per iter Bc=64 kcols. 8 warps, warp m-slice = 16 rows.
#define QP 132                               // pitch (floats) for Qs/Ks
#define PP 68                                // pitch for Vs/Ps
// floats: Qs 128*132, Ks 64*132, Vs 128*68, Ps 128*68
#define ATTN2_SMEM ((128 * QP + 64 * QP + 128 * PP + 128 * PP) * 4)

__global__ __launch_bounds__(256, 1)
void attn_mma(const float* __restrict__ Qg_, const float* __restrict__ Kg_,
              const float* __restrict__ Vt_, float* __restrict__ Y) {
    extern __shared__ float sm[];
    float* Qs = sm;                          // [128][QP]  rows=qrow cols=d
    float* Ks = Qs + 128 * QP;               // [64][QP]   rows=kcol cols=d
    float* Vs = Ks + 64 * QP;                // [128][PP]  rows=d    cols=kcol
    float* Ps = Vs + 128 * PP;               // [128][PP]  rows=qrow cols=kcol

    const int tid  = threadIdx.x;
    const int wid  = tid >> 5;
    const int lane = tid & 31;
    const int qb = gridDim.x - 1 - blockIdx.x;   // heavy tiles first
    const int h  = blockIdx.y;
    const int b  = blockIdx.z;
    const int q0 = qb * 128;

    const size_t bh = (size_t)(b * HH + h);
    const float* Qg = Qg_ + bh * SS * DD;    // [s][d]
    const float* Kg = Kg_ + bh * SS * DD;    // [s][d]
    const float* Vg = Vt_ + bh * DD * SS;    // [d][s]

    // load Q tile (scale folded, tf32-rounded)
    const float scale = 0.088388347648318447f;
#pragma unroll
    for (int p = 0; p < 16; p++) {
        int idx = tid + p * 256;
        int row = idx >> 5, ch = idx & 31;
        float4 v = *(const float4*)&Qg[(size_t)(q0 + row) * DD + ch * 4];
        v.x *= scale; v.y *= scale; v.z *= scale; v.w *= scale;
        *(float4*)&Qs[row * QP + ch * 4] = round4(v);
    }

    const int sub = lane >> 3, r8 = lane & 7;
    const int g = lane >> 2, qq = lane & 3;
    const uint32_t a_q = smem_u32(Qs) + (uint32_t)((wid * 16 + (sub & 1) * 8 + r8) * QP + (sub >> 1) * 4) * 4;
    const uint32_t b_k = smem_u32(Ks) + (uint32_t)(((sub >> 1) * 8 + r8) * QP + (sub & 1) * 4) * 4;
    const uint32_t a_p = smem_u32(Ps) + (uint32_t)((wid * 16 + (sub & 1) * 8 + r8) * PP + (sub >> 1) * 4) * 4;
    const uint32_t b_v = smem_u32(Vs) + (uint32_t)(((sub >> 1) * 8 + r8) * PP + (sub & 1) * 4) * 4;

    float o[16][4];
#pragma unroll
    for (int i = 0; i < 16; i++)
#pragma unroll
        for (int j = 0; j < 4; j++) o[i][j] = 0.f;
    float m0v = -1e30f, m1v = -1e30f, l0 = 0.f, l1 = 0.f;

    const int nkt = 2 * qb + 2;
    for (int kt = 0; kt < nkt; kt++) {
        const int k0 = kt * 64;
        __syncthreads();
        // K tile: [64][128]
#pragma unroll
        for (int p = 0; p < 8; p++) {
            int idx = tid + p * 256;
            int row = idx >> 5, ch = idx & 31;
            *(float4*)&Ks[row * QP + ch * 4] =
                round4(*(const float4*)&Kg[(size_t)(k0 + row) * DD + ch * 4]);
        }
        // V tile: [128 d][64 kcol]
#pragma unroll
        for (int p = 0; p < 8; p++) {
            int idx = tid + p * 256;
            int row = idx >> 4, ch = idx & 15;
            *(float4*)&Vs[row * PP + ch * 4] =
                round4(*(const float4*)&Vg[(size_t)row * SS + k0 + ch * 4]);
        }
        __syncthreads();

        // S = Q K^T
        float s[8][4];
#pragma unroll
        for (int i = 0; i < 8; i++)
#pragma unroll
            for (int j = 0; j < 4; j++) s[i][j] = 0.f;
#pragma unroll
        for (int kd = 0; kd < 16; kd++) {
            uint32_t a[4];
            LDSM4(a, a_q + kd * 32);
            uint32_t bf[4][4];
#pragma unroll
            for (int nt = 0; nt < 4; nt++)
                LDSM4(bf[nt], b_k + (uint32_t)(nt * 16 * QP) * 4 + kd * 32);
#pragma unroll
            for (int nt = 0; nt < 4; nt++) {
                MMA_TF32(s[nt * 2],     a, bf[nt][0], bf[nt][1]);
                MMA_TF32(s[nt * 2 + 1], a, bf[nt][2], bf[nt][3]);
            }
        }

        // causal mask (only last two tiles)
        if (kt >= 2 * qb) {
            int row0 = q0 + wid * 16 + g;
#pragma unroll
            for (int j = 0; j < 8; j++) {
                int c = k0 + j * 8 + qq * 2;
                if (c     > row0)     s[j][0] = -1e30f;
                if (c + 1 > row0)     s[j][1] = -1e30f;
                if (c     > row0 + 8) s[j][2] = -1e30f;
                if (c + 1 > row0 + 8) s[j][3] = -1e30f;
            }
        }

        // online softmax (rows g, g+8; quad holds 64-col row slices)
        float tm0 = -1e30f, tm1 = -1e30f;
#pragma unroll
        for (int j = 0; j < 8; j++) {
            tm0 = fmaxf(tm0, fmaxf(s[j][0], s[j][1]));
            tm1 = fmaxf(tm1, fmaxf(s[j][2], s[j][3]));
        }
        tm0 = fmaxf(tm0, __shfl_xor_sync(0xffffffffu, tm0, 1));
        tm0 = fmaxf(tm0, __shfl_xor_sync(0xffffffffu, tm0, 2));
        tm1 = fmaxf(tm1, __shfl_xor_sync(0xffffffffu, tm1, 1));
        tm1 = fmaxf(tm1, __shfl_xor_sync(0xffffffffu, tm1, 2));
        float mn0 = fmaxf(m0v, tm0), mn1 = fmaxf(m1v, tm1);
        float al0 = __expf(m0v - mn0), al1 = __expf(m1v - mn1);
        m0v = mn0; m1v = mn1;
        float rs0 = 0.f, rs1 = 0.f;
#pragma unroll
        for (int j = 0; j < 8; j++) {
            s[j][0] = __expf(s[j][0] - mn0);
            s[j][1] = __expf(s[j][1] - mn0);
            s[j][2] = __expf(s[j][2] - mn1);
            s[j][3] = __expf(s[j][3] - mn1);
            rs0 += s[j][0] + s[j][1];
            rs1 += s[j][2] + s[j][3];
        }
        rs0 += __shfl_xor_sync(0xffffffffu, rs0, 1);
        rs0 += __shfl_xor_sync(0xffffffffu, rs0, 2);
        rs1 += __shfl_xor_sync(0xffffffffu, rs1, 1);
        rs1 += __shfl_xor_sync(0xffffffffu, rs1, 2);
        l0 = l0 * al0 + rs0;
        l1 = l1 * al1 + rs1;
#pragma unroll
        for (int nt = 0; nt < 16; nt++) {
            o[nt][0] *= al0; o[nt][1] *= al0;
            o[nt][2] *= al1; o[nt][3] *= al1;
        }

        // stage P (warp-private rows), tf32-rounded
        {
            int pr0 = (wid * 16 + g) * PP;
#pragma unroll
            for (int j = 0; j < 8; j++) {
                *(float2*)&Ps[pr0 + j * 8 + qq * 2] =
                    make_float2(to_tf32(s[j][0]), to_tf32(s[j][1]));
                *(float2*)&Ps[pr0 + 8 * PP + j * 8 + qq * 2] =
                    make_float2(to_tf32(s[j][2]), to_tf32(s[j][3]));
            }
        }
        __syncwarp();

        // O += P @ V
#pragma unroll
        for (int jk = 0; jk < 8; jk++) {
            uint32_t a[4];
            LDSM4(a, a_p + jk * 32);
#pragma unroll
            for (int nt = 0; nt < 8; nt++) {
                uint32_t bf[4];
                LDSM4(bf, b_v + (uint32_t)(nt * 16 * PP) * 4 + jk * 32);
                MMA_TF32(o[nt * 2],     a, bf[0], bf[1]);
                MMA_TF32(o[nt * 2 + 1], a, bf[2], bf[3]);
            }
        }
    }

    // normalize + tf32-round + write Y [b,s,h,d]
    float i0 = 1.f / l0, i1 = 1.f / l1;
    int row0 = q0 + wid * 16 + g;
    size_t base0 = ((size_t)b * SS + row0) * EE + h * 128;
    size_t base1 = base0 + (size_t)8 * EE;
#pragma unroll
    for (int nt = 0; nt < 16; nt++) {
        int col = nt * 8 + qq * 2;
        *(float2*)&Y[base0 + col] =
            make_float2(to_tf32(o[nt][0] * i0), to_tf32(o[nt][1] * i0));
        *(float2*)&Y[base1 + col] =
            make_float2(to_tf32(o[nt][2] * i1), to_tf32(o[nt][3] * i1));
    }
}

// ---------------- launch -----------------------------------------------------
extern "C" void kernel_launch(void* const* d_in, const int* in_sizes, int n_in,
                              void* d_out, int out_size) {
    const float* x     = (const float*)d_in[0];
    const float* w_qkv = (const float*)d_in[1];
    const float* w_out = (const float*)d_in[2];
    float* out = (float*)d_out;

    float *p_x, *p_wqkv, *p_wout, *p_qkv, *p_Q, *p_K, *p_Vt, *p_y;
    cudaGetSymbolAddress((void**)&p_x,    g_x);
    cudaGetSymbolAddress((void**)&p_wqkv, g_wqkv);
    cudaGetSymbolAddress((void**)&p_wout, g_wout);
    cudaGetSymbolAddress((void**)&p_qkv,  g_qkv);
    cudaGetSymbolAddress((void**)&p_Q,    g_Q);
    cudaGetSymbolAddress((void**)&p_K,    g_K);
    cudaGetSymbolAddress((void**)&p_Vt,   g_Vt);
    cudaGetSymbolAddress((void**)&p_y,    g_y);

    cudaFuncSetAttribute(gemm_mma, cudaFuncAttributeMaxDynamicSharedMemorySize, GEMM_SMEM);
    cudaFuncSetAttribute(attn_mma, cudaFuncAttributeMaxDynamicSharedMemorySize, ATTN2_SMEM);

    // 0) round GEMM operands to tf32 (RNA)
    round_tf32_k<<<(MROWS * EE / 4 + 255) / 256, 256>>>((const float4*)x, (float4*)p_x, MROWS * EE / 4);
    round_tf32_k<<<(QKV_N * EE / 4 + 255) / 256, 256>>>((const float4*)w_qkv, (float4*)p_wqkv, QKV_N * EE / 4);
    round_tf32_k<<<(EE * EE / 4 + 255) / 256, 256>>>((const float4*)w_out, (float4*)p_wout, EE * EE / 4);

    // 1) qkv = x @ w_qkv^T
    gemm_mma<<<dim3(QKV_N / 128, MROWS / 128), 256, GEMM_SMEM>>>(p_x, p_wqkv, p_qkv, QKV_N, EE);
    // 2) RoPE → Q,K [b,h,s,d]; V transpose → [b,h,d,s]
    rope_qk<<<(BB * HH * SS * DD) / 256, 256>>>(p_qkv, p_Q, p_K);
    transpose_v<<<dim3(SS / 32, DD / 32, BB * HH), dim3(32, 8)>>>(p_qkv, p_Vt);
    // 3) flash attention (mma.sync tf32)
    attn_mma<<<dim3(SS / 128, HH, BB), 256, ATTN2_SMEM>>>(p_Q, p_K, p_Vt, p_y);
    // 4) out = y @ w_out^T
    gemm_mma<<<dim3(EE / 128, MROWS / 128), 256, GEMM_SMEM>>>(p_y, p_wout, out, EE, EE);
}

// round 5
// speedup vs baseline: 3.5332x; 1.0600x over previous
#include <cuda_runtime.h>
#include <cuda_bf16.h>
#include <cstdint>
#include <math.h>

// Problem constants
#define BB 2
#define SS 2048
#define EE 2048
#define HH 16
#define DD 128
#define MROWS (BB * SS)          // 4096
#define QKV_N (3 * EE)           // 6144

// ---------------- scratch (device globals: allocation-free) ----------------
__device__ float g_x   [(size_t)MROWS * EE];            // tf32-rounded x
__device__ float g_wqkv[(size_t)QKV_N * EE];            // tf32-rounded w_qkv
__device__ float g_wout[(size_t)EE * EE];               // tf32-rounded w_out
__device__ float g_qkv [(size_t)MROWS * QKV_N];         // [4096, 6144] fp32
__device__ float g_Q   [(size_t)BB * HH * SS * DD];     // [b,h,s,d] (roped)
__device__ float g_K   [(size_t)BB * HH * SS * DD];     // [b,h,s,d] (roped)
__device__ float g_Vt  [(size_t)BB * HH * DD * SS];     // [b,h,d,s]
__device__ float g_y   [(size_t)MROWS * EE];            // [b,s,h,d], tf32-rounded

// ======================= helpers ===========================================
__device__ __forceinline__ uint32_t smem_u32(const void* p) {
    uint32_t a;
    asm("{ .reg .u64 t; cvta.to.shared.u64 t, %1; cvt.u32.u64 %0, t; }"
        : "=r"(a) : "l"(p));
    return a;
}

__device__ __forceinline__ float to_tf32(float x) {
    uint32_t u;
    asm("cvt.rna.tf32.f32 %0, %1;" : "=r"(u) : "f"(x));
    return __uint_as_float(u);
}

__device__ __forceinline__ float4 round4(float4 v) {
    v.x = to_tf32(v.x); v.y = to_tf32(v.y);
    v.z = to_tf32(v.z); v.w = to_tf32(v.w);
    return v;
}

#define CPA16(dst, src) \
    asm volatile("cp.async.cg.shared.global [%0], [%1], 16;" :: "r"(dst), "l"(src))
#define CPA_COMMIT()  asm volatile("cp.async.commit_group;" ::: "memory")
#define CPA_WAIT1()   asm volatile("cp.async.wait_group 1;" ::: "memory")

#define LDSM4(r, addr)                                                        \
    asm volatile("ldmatrix.sync.aligned.m8n8.x4.shared.b16 {%0,%1,%2,%3}, [%4];" \
        : "=r"((r)[0]), "=r"((r)[1]), "=r"((r)[2]), "=r"((r)[3]) : "r"(addr))

#define MMA_TF32(c, a, b0, b1)                                                \
    asm volatile("mma.sync.aligned.m16n8k8.row.col.f32.tf32.tf32.f32 "        \
        "{%0,%1,%2,%3}, {%4,%5,%6,%7}, {%8,%9}, {%0,%1,%2,%3};"               \
        : "+f"((c)[0]), "+f"((c)[1]), "+f"((c)[2]), "+f"((c)[3])              \
        : "r"((a)[0]), "r"((a)[1]), "r"((a)[2]), "r"((a)[3]), "r"(b0), "r"(b1))

// ============ mma.sync tf32 GEMM: C[M,N] = A[M,K] @ B[N,K]^T ===============
// CTA 128x256, 8 warps (2m x 4n), warptile 64x64, K-chunk 32, 3-stage cp.async
#define GP 36                                // SMEM pitch (floats), %32==4
#define BOFF (128 * GP * 4)                  // B offset within stage (bytes)
#define STG_B ((128 + 256) * GP * 4)         // 55296 bytes
#define GEMM_SMEM (3 * STG_B)                // 165888 bytes

__device__ __forceinline__ void g2s_stage(const float* A, const float* B, int K,
                                          uint32_t stg, int tid) {
#pragma unroll
    for (int j = 0; j < 4; j++) {            // A: 128 rows x 8 chunks
        int cid = tid + j * 256;
        int row = cid >> 3, chk = cid & 7;
        CPA16(stg + (uint32_t)(row * GP + chk * 4) * 4,
              A + (size_t)row * K + chk * 4);
    }
#pragma unroll
    for (int j = 0; j < 8; j++) {            // B: 256 rows x 8 chunks
        int cid = tid + j * 256;
        int row = cid >> 3, chk = cid & 7;
        CPA16(stg + BOFF + (uint32_t)(row * GP + chk * 4) * 4,
              B + (size_t)row * K + chk * 4);
    }
}

__global__ __launch_bounds__(256, 1)
void gemm_mma(const float* __restrict__ A, const float* __restrict__ B,
              float* __restrict__ C, int N, int K) {
    extern __shared__ char smem[];
    const uint32_t sbase = smem_u32(smem);
    const int tid  = threadIdx.x;
    const int wid  = tid >> 5;
    const int lane = tid & 31;
    const int wm   = wid >> 2;               // 0..1 (64 rows)
    const int wn   = wid & 3;                // 0..3 (64 cols)
    const int m0 = blockIdx.y * 128;
    const int n0 = blockIdx.x * 256;
    const int iters = K >> 5;

    const float* Ab = A + (size_t)m0 * K;
    const float* Bb = B + (size_t)n0 * K;

    float c[4][8][4];
#pragma unroll
    for (int i = 0; i < 4; i++)
#pragma unroll
        for (int j = 0; j < 8; j++)
#pragma unroll
            for (int q = 0; q < 4; q++) c[i][j][q] = 0.f;

    const int sub = lane >> 3;
    const int r8  = lane & 7;
    const uint32_t aoff = (uint32_t)((wm * 64 + (sub & 1) * 8 + r8) * GP + (sub >> 1) * 4) * 4;
    const uint32_t boff = BOFF + (uint32_t)((wn * 64 + (sub >> 1) * 8 + r8) * GP + (sub & 1) * 4) * 4;

    g2s_stage(Ab, Bb, K, sbase, tid);                   CPA_COMMIT();
    g2s_stage(Ab + 32, Bb + 32, K, sbase + STG_B, tid); CPA_COMMIT();

    for (int i = 0; i < iters; i++) {
        CPA_WAIT1();
        __syncthreads();
        if (i + 2 < iters) {
            uint32_t stg = sbase + (uint32_t)((i + 2) % 3) * STG_B;
            g2s_stage(Ab + (i + 2) * 32, Bb + (i + 2) * 32, K, stg, tid);
            CPA_COMMIT();
        }
        const uint32_t ab = sbase + (uint32_t)(i % 3) * STG_B + aoff;
        const uint32_t bb = sbase + (uint32_t)(i % 3) * STG_B + boff;

        uint32_t a[2][4][4], bf[2][4][4];
        // preload k-step 0 fragments
#pragma unroll
        for (int im = 0; im < 4; im++)
            LDSM4(a[0][im], ab + (uint32_t)(im * 16 * GP) * 4);
#pragma unroll
        for (int nt = 0; nt < 4; nt++)
            LDSM4(bf[0][nt], bb + (uint32_t)(nt * 16 * GP) * 4);

#pragma unroll
        for (int kk = 0; kk < 4; kk++) {
            int cur = kk & 1, nxt = cur ^ 1;
            if (kk < 3) {
#pragma unroll
                for (int im = 0; im < 4; im++)
                    LDSM4(a[nxt][im], ab + (uint32_t)(im * 16 * GP) * 4 + (kk + 1) * 32);
#pragma unroll
                for (int nt = 0; nt < 4; nt++)
                    LDSM4(bf[nxt][nt], bb + (uint32_t)(nt * 16 * GP) * 4 + (kk + 1) * 32);
            }
#pragma unroll
            for (int im = 0; im < 4; im++)
#pragma unroll
                for (int jn = 0; jn < 8; jn++)
                    MMA_TF32(c[im][jn], a[cur][im],
                             bf[cur][jn >> 1][(jn & 1) * 2],
                             bf[cur][jn >> 1][(jn & 1) * 2 + 1]);
        }
    }

    const int g = lane >> 2, q = lane & 3;
#pragma unroll
    for (int im = 0; im < 4; im++)
#pragma unroll
        for (int jn = 0; jn < 8; jn++) {
            int row = m0 + wm * 64 + im * 16 + g;
            int col = n0 + wn * 64 + jn * 8 + q * 2;
            *(float2*)&C[(size_t)row * N + col]       = make_float2(c[im][jn][0], c[im][jn][1]);
            *(float2*)&C[(size_t)(row + 8) * N + col] = make_float2(c[im][jn][2], c[im][jn][3]);
        }
}

// ---------------- tf32 round-to-nearest copy -------------------------------
__global__ void round_tf32_k(const float4* __restrict__ in, float4* __restrict__ out, int n4) {
    int i = blockIdx.x * blockDim.x + threadIdx.x;
    if (i >= n4) return;
    out[i] = round4(in[i]);
}

// ---------------- RoPE for Q,K → [b,h,s,d] ---------------------------------
__global__ void rope_qk(const float* __restrict__ qkv,
                        float* __restrict__ Q, float* __restrict__ K) {
    int idx = blockIdx.x * blockDim.x + threadIdx.x;
    int d  = idx & 127;
    int s  = (idx >> 7) & 2047;
    int bh = idx >> 18;
    int i  = d & 63;
    float theta = (float)s * exp2f(-0.20762050593045998f * (float)i);
    float sn, cs;
    sincosf(theta, &sn, &cs);
    const float* row = qkv + (size_t)((bh >> 4) * 2048 + s) * QKV_N;
    int nq = (bh & 15) * 128;
    float qv = row[nq + d];
    float qp = row[nq + (d ^ 64)];
    float kv = row[2048 + nq + d];
    float kp = row[2048 + nq + (d ^ 64)];
    float qr = (d < 64) ? -qp : qp;
    float kr = (d < 64) ? -kp : kp;
    Q[idx] = qv * cs + qr * sn;
    K[idx] = kv * cs + kr * sn;
}

// ---------------- V transpose → [b,h,d,s] ----------------------------------
__global__ void transpose_v(const float* __restrict__ qkv, float* __restrict__ Vt) {
    __shared__ float t[32][33];
    int bh = blockIdx.z;
    int b = bh >> 4, h = bh & 15;
    int s0 = blockIdx.x * 32, d0 = blockIdx.y * 32;
    int tx = threadIdx.x, ty = threadIdx.y;
    const float* src = qkv + ((size_t)(b * SS + s0 + ty)) * QKV_N + 4096 + h * 128 + d0 + tx;
#pragma unroll
    for (int j = 0; j < 32; j += 8)
        t[ty + j][tx] = src[(size_t)j * QKV_N];
    __syncthreads();
    float* dst = Vt + ((size_t)bh * DD + d0 + ty) * SS + s0 + tx;
#pragma unroll
    for (int j = 0; j < 32; j += 8)
        dst[(size_t)j * SS] = t[tx][ty + j];
}

// ---------------- Flash attention via mma.sync tf32 ------------------------
#define QP 132                               // pitch (floats) for Qs/Ks
#define PP 68                                // pitch for Vs/Ps
#define ATTN2_SMEM ((128 * QP + 64 * QP + 128 * PP + 128 * PP) * 4)

__global__ __launch_bounds__(256, 1)
void attn_mma(const float* __restrict__ Qg_, const float* __restrict__ Kg_,
              const float* __restrict__ Vt_, float* __restrict__ Y) {
    extern __shared__ float sm[];
    float* Qs = sm;                          // [128][QP]  rows=qrow cols=d
    float* Ks = Qs + 128 * QP;               // [64][QP]   rows=kcol cols=d
    float* Vs = Ks + 64 * QP;                // [128][PP]  rows=d    cols=kcol
    float* Ps = Vs + 128 * PP;               // [128][PP]  rows=qrow cols=kcol

    const int tid  = threadIdx.x;
    const int wid  = tid >> 5;
    const int lane = tid & 31;
    const int qb = gridDim.x - 1 - blockIdx.x;
    const int h  = blockIdx.y;
    const int b  = blockIdx.z;
    const int q0 = qb * 128;

    const size_t bh = (size_t)(b * HH + h);
    const float* Qg = Qg_ + bh * SS * DD;
    const float* Kg = Kg_ + bh * SS * DD;
    const float* Vg = Vt_ + bh * DD * SS;

    const float scale = 0.088388347648318447f;
#pragma unroll
    for (int p = 0; p < 16; p++) {
        int idx = tid + p * 256;
        int row = idx >> 5, ch = idx & 31;
        float4 v = *(const float4*)&Qg[(size_t)(q0 + row) * DD + ch * 4];
        v.x *= scale; v.y *= scale; v.z *= scale; v.w *= scale;
        *(float4*)&Qs[row * QP + ch * 4] = round4(v);
    }

    const int sub = lane >> 3, r8 = lane & 7;
    const int g = lane >> 2, qq = lane & 3;
    const uint32_t a_q = smem_u32(Qs) + (uint32_t)((wid * 16 + (sub & 1) * 8 + r8) * QP + (sub >> 1) * 4) * 4;
    const uint32_t b_k = smem_u32(Ks) + (uint32_t)(((sub >> 1) * 8 + r8) * QP + (sub & 1) * 4) * 4;
    const uint32_t a_p = smem_u32(Ps) + (uint32_t)((wid * 16 + (sub & 1) * 8 + r8) * PP + (sub >> 1) * 4) * 4;
    const uint32_t b_v = smem_u32(Vs) + (uint32_t)(((sub >> 1) * 8 + r8) * PP + (sub & 1) * 4) * 4;

    float o[16][4];
#pragma unroll
    for (int i = 0; i < 16; i++)
#pragma unroll
        for (int j = 0; j < 4; j++) o[i][j] = 0.f;
    float m0v = -1e30f, m1v = -1e30f, l0 = 0.f, l1 = 0.f;

    const int nkt = 2 * qb + 2;
    for (int kt = 0; kt < nkt; kt++) {
        const int k0 = kt * 64;
        __syncthreads();
#pragma unroll
        for (int p = 0; p < 8; p++) {
            int idx = tid + p * 256;
            int row = idx >> 5, ch = idx & 31;
            *(float4*)&Ks[row * QP + ch * 4] =
                round4(*(const float4*)&Kg[(size_t)(k0 + row) * DD + ch * 4]);
        }
#pragma unroll
        for (int p = 0; p < 8; p++) {
            int idx = tid + p * 256;
            int row = idx >> 4, ch = idx & 15;
            *(float4*)&Vs[row * PP + ch * 4] =
                round4(*(const float4*)&Vg[(size_t)row * SS + k0 + ch * 4]);
        }
        __syncthreads();

        float s[8][4];
#pragma unroll
        for (int i = 0; i < 8; i++)
#pragma unroll
            for (int j = 0; j < 4; j++) s[i][j] = 0.f;
#pragma unroll
        for (int kd = 0; kd < 16; kd++) {
            uint32_t a[4];
            LDSM4(a, a_q + kd * 32);
            uint32_t bf[4][4];
#pragma unroll
            for (int nt = 0; nt < 4; nt++)
                LDSM4(bf[nt], b_k + (uint32_t)(nt * 16 * QP) * 4 + kd * 32);
#pragma unroll
            for (int nt = 0; nt < 4; nt++) {
                MMA_TF32(s[nt * 2],     a, bf[nt][0], bf[nt][1]);
                MMA_TF32(s[nt * 2 + 1], a, bf[nt][2], bf[nt][3]);
            }
        }

        if (kt >= 2 * qb) {
            int row0 = q0 + wid * 16 + g;
#pragma unroll
            for (int j = 0; j < 8; j++) {
                int c = k0 + j * 8 + qq * 2;
                if (c     > row0)     s[j][0] = -1e30f;
                if (c + 1 > row0)     s[j][1] = -1e30f;
                if (c     > row0 + 8) s[j][2] = -1e30f;
                if (c + 1 > row0 + 8) s[j][3] = -1e30f;
            }
        }

        float tm0 = -1e30f, tm1 = -1e30f;
#pragma unroll
        for (int j = 0; j < 8; j++) {
            tm0 = fmaxf(tm0, fmaxf(s[j][0], s[j][1]));
            tm1 = fmaxf(tm1, fmaxf(s[j][2], s[j][3]));
        }
        tm0 = fmaxf(tm0, __shfl_xor_sync(0xffffffffu, tm0, 1));
        tm0 = fmaxf(tm0, __shfl_xor_sync(0xffffffffu, tm0, 2));
        tm1 = fmaxf(tm1, __shfl_xor_sync(0xffffffffu, tm1, 1));
        tm1 = fmaxf(tm1, __shfl_xor_sync(0xffffffffu, tm1, 2));
        float mn0 = fmaxf(m0v, tm0), mn1 = fmaxf(m1v, tm1);
        float al0 = __expf(m0v - mn0), al1 = __expf(m1v - mn1);
        m0v = mn0; m1v = mn1;
        float rs0 = 0.f, rs1 = 0.f;
#pragma unroll
        for (int j = 0; j < 8; j++) {
            s[j][0] = __expf(s[j][0] - mn0);
            s[j][1] = __expf(s[j][1] - mn0);
            s[j][2] = __expf(s[j][2] - mn1);
            s[j][3] = __expf(s[j][3] - mn1);
            rs0 += s[j][0] + s[j][1];
            rs1 += s[j][2] + s[j][3];
        }
        rs0 += __shfl_xor_sync(0xffffffffu, rs0, 1);
        rs0 += __shfl_xor_sync(0xffffffffu, rs0, 2);
        rs1 += __shfl_xor_sync(0xffffffffu, rs1, 1);
        rs1 += __shfl_xor_sync(0xffffffffu, rs1, 2);
        l0 = l0 * al0 + rs0;
        l1 = l1 * al1 + rs1;
#pragma unroll
        for (int nt = 0; nt < 16; nt++) {
            o[nt][0] *= al0; o[nt][1] *= al0;
            o[nt][2] *= al1; o[nt][3] *= al1;
        }

        {
            int pr0 = (wid * 16 + g) * PP;
#pragma unroll
            for (int j = 0; j < 8; j++) {
                *(float2*)&Ps[pr0 + j * 8 + qq * 2] =
                    make_float2(to_tf32(s[j][0]), to_tf32(s[j][1]));
                *(float2*)&Ps[pr0 + 8 * PP + j * 8 + qq * 2] =
                    make_float2(to_tf32(s[j][2]), to_tf32(s[j][3]));
            }
        }
        __syncwarp();

#pragma unroll
        for (int jk = 0; jk < 8; jk++) {
            uint32_t a[4];
            LDSM4(a, a_p + jk * 32);
#pragma unroll
            for (int nt = 0; nt < 8; nt++) {
                uint32_t bf[4];
                LDSM4(bf, b_v + (uint32_t)(nt * 16 * PP) * 4 + jk * 32);
                MMA_TF32(o[nt * 2],     a, bf[0], bf[1]);
                MMA_TF32(o[nt * 2 + 1], a, bf[2], bf[3]);
            }
        }
    }

    float i0 = 1.f / l0, i1 = 1.f / l1;
    int row0 = q0 + wid * 16 + g;
    size_t base0 = ((size_t)b * SS + row0) * EE + h * 128;
    size_t base1 = base0 + (size_t)8 * EE;
#pragma unroll
    for (int nt = 0; nt < 16; nt++) {
        int col = nt * 8 + qq * 2;
        *(float2*)&Y[base0 + col] =
            make_float2(to_tf32(o[nt][0] * i0), to_tf32(o[nt][1] * i0));
        *(float2*)&Y[base1 + col] =
            make_float2(to_tf32(o[nt][2] * i1), to_tf32(o[nt][3] * i1));
    }
}

// ---------------- launch -----------------------------------------------------
extern "C" void kernel_launch(void* const* d_in, const int* in_sizes, int n_in,
                              void* d_out, int out_size) {
    const float* x     = (const float*)d_in[0];
    const float* w_qkv = (const float*)d_in[1];
    const float* w_out = (const float*)d_in[2];
    float* out = (float*)d_out;

    float *p_x, *p_wqkv, *p_wout, *p_qkv, *p_Q, *p_K, *p_Vt, *p_y;
    cudaGetSymbolAddress((void**)&p_x,    g_x);
    cudaGetSymbolAddress((void**)&p_wqkv, g_wqkv);
    cudaGetSymbolAddress((void**)&p_wout, g_wout);
    cudaGetSymbolAddress((void**)&p_qkv,  g_qkv);
    cudaGetSymbolAddress((void**)&p_Q,    g_Q);
    cudaGetSymbolAddress((void**)&p_K,    g_K);
    cudaGetSymbolAddress((void**)&p_Vt,   g_Vt);
    cudaGetSymbolAddress((void**)&p_y,    g_y);

    cudaFuncSetAttribute(gemm_mma, cudaFuncAttributeMaxDynamicSharedMemorySize, GEMM_SMEM);
    cudaFuncSetAttribute(attn_mma, cudaFuncAttributeMaxDynamicSharedMemorySize, ATTN2_SMEM);

    // 0) round GEMM operands to tf32 (RNA)
    round_tf32_k<<<(MROWS * EE / 4 + 255) / 256, 256>>>((const float4*)x, (float4*)p_x, MROWS * EE / 4);
    round_tf32_k<<<(QKV_N * EE / 4 + 255) / 256, 256>>>((const float4*)w_qkv, (float4*)p_wqkv, QKV_N * EE / 4);
    round_tf32_k<<<(EE * EE / 4 + 255) / 256, 256>>>((const float4*)w_out, (float4*)p_wout, EE * EE / 4);

    // 1) qkv = x @ w_qkv^T
    gemm_mma<<<dim3(QKV_N / 256, MROWS / 128), 256, GEMM_SMEM>>>(p_x, p_wqkv, p_qkv, QKV_N, EE);
    // 2) RoPE → Q,K [b,h,s,d]; V transpose → [b,h,d,s]
    rope_qk<<<(BB * HH * SS * DD) / 256, 256>>>(p_qkv, p_Q, p_K);
    transpose_v<<<dim3(SS / 32, DD / 32, BB * HH), dim3(32, 8)>>>(p_qkv, p_Vt);
    // 3) flash attention (mma.sync tf32)
    attn_mma<<<dim3(SS / 128, HH, BB), 256, ATTN2_SMEM>>>(p_Q, p_K, p_Vt, p_y);
    // 4) out = y @ w_out^T
    gemm_mma<<<dim3(EE / 256, MROWS / 128), 256, GEMM_SMEM>>>(p_y, p_wout, out, EE, EE);
}

// round 6
// speedup vs baseline: 3.6313x; 1.0277x over previous
#include <cuda_runtime.h>
#include <cuda_bf16.h>
#include <cstdint>
#include <math.h>

// Problem constants
#define BB 2
#define SS 2048
#define EE 2048
#define HH 16
#define DD 128
#define MROWS (BB * SS)          // 4096
#define QKV_N (3 * EE)           // 6144

// ---------------- scratch (device globals: allocation-free) ----------------
__device__ float g_x   [(size_t)MROWS * EE];            // tf32-rounded x
__device__ float g_wqkv[(size_t)QKV_N * EE];            // tf32-rounded w_qkv
__device__ float g_wout[(size_t)EE * EE];               // tf32-rounded w_out
__device__ float g_qkv [(size_t)MROWS * QKV_N];         // [4096, 6144] fp32
__device__ float g_Q   [(size_t)BB * HH * SS * DD];     // [b,h,s,d] (roped)
__device__ float g_K   [(size_t)BB * HH * SS * DD];     // [b,h,s,d] (roped)
__device__ float g_Vt  [(size_t)BB * HH * DD * SS];     // [b,h,d,s]
__device__ float g_y   [(size_t)MROWS * EE];            // [b,s,h,d], tf32-rounded

// ======================= helpers ===========================================
__device__ __forceinline__ uint32_t smem_u32(const void* p) {
    uint32_t a;
    asm("{ .reg .u64 t; cvta.to.shared.u64 t, %1; cvt.u32.u64 %0, t; }"
        : "=r"(a) : "l"(p));
    return a;
}

__device__ __forceinline__ float to_tf32(float x) {
    uint32_t u;
    asm("cvt.rna.tf32.f32 %0, %1;" : "=r"(u) : "f"(x));
    return __uint_as_float(u);
}

__device__ __forceinline__ float4 round4(float4 v) {
    v.x = to_tf32(v.x); v.y = to_tf32(v.y);
    v.z = to_tf32(v.z); v.w = to_tf32(v.w);
    return v;
}

#define CPA16(dst, src) \
    asm volatile("cp.async.cg.shared.global [%0], [%1], 16;" :: "r"(dst), "l"(src))
#define CPA_COMMIT()  asm volatile("cp.async.commit_group;" ::: "memory")
#define CPA_WAIT1()   asm volatile("cp.async.wait_group 1;" ::: "memory")

#define LDSM4(r, addr)                                                        \
    asm volatile("ldmatrix.sync.aligned.m8n8.x4.shared.b16 {%0,%1,%2,%3}, [%4];" \
        : "=r"((r)[0]), "=r"((r)[1]), "=r"((r)[2]), "=r"((r)[3]) : "r"(addr))

#define MMA_TF32(c, a, b0, b1)                                                \
    asm volatile("mma.sync.aligned.m16n8k8.row.col.f32.tf32.tf32.f32 "        \
        "{%0,%1,%2,%3}, {%4,%5,%6,%7}, {%8,%9}, {%0,%1,%2,%3};"               \
        : "+f"((c)[0]), "+f"((c)[1]), "+f"((c)[2]), "+f"((c)[3])              \
        : "r"((a)[0]), "r"((a)[1]), "r"((a)[2]), "r"((a)[3]), "r"(b0), "r"(b1))

// ============ mma.sync tf32 GEMM: C[M,N] = A[M,K] @ B[N,K]^T ===============
// CTA 128x256, 512 thr / 16 warps (4m x 4n), warptile 32x64, 3-stage cp.async
#define GP 36                                // SMEM pitch (floats), %32==4
#define BOFF (128 * GP * 4)                  // B offset within stage (bytes)
#define STG_B ((128 + 256) * GP * 4)         // 55296 bytes
#define GEMM_SMEM (3 * STG_B)                // 165888 bytes

__device__ __forceinline__ void g2s_stage(const float* A, const float* B, int K,
                                          uint32_t stg, int tid) {
#pragma unroll
    for (int j = 0; j < 2; j++) {            // A: 128 rows x 8 chunks
        int cid = tid + j * 512;
        int row = cid >> 3, chk = cid & 7;
        CPA16(stg + (uint32_t)(row * GP + chk * 4) * 4,
              A + (size_t)row * K + chk * 4);
    }
#pragma unroll
    for (int j = 0; j < 4; j++) {            // B: 256 rows x 8 chunks
        int cid = tid + j * 512;
        int row = cid >> 3, chk = cid & 7;
        CPA16(stg + BOFF + (uint32_t)(row * GP + chk * 4) * 4,
              B + (size_t)row * K + chk * 4);
    }
}

__global__ __launch_bounds__(512, 1)
void gemm_mma(const float* __restrict__ A, const float* __restrict__ B,
              float* __restrict__ C, int N, int K) {
    extern __shared__ char smem[];
    const uint32_t sbase = smem_u32(smem);
    const int tid  = threadIdx.x;
    const int wid  = tid >> 5;
    const int lane = tid & 31;
    const int wm   = wid >> 2;               // 0..3 (32 rows)
    const int wn   = wid & 3;                // 0..3 (64 cols)
    const int m0 = blockIdx.y * 128;
    const int n0 = blockIdx.x * 256;
    const int iters = K >> 5;

    const float* Ab = A + (size_t)m0 * K;
    const float* Bb = B + (size_t)n0 * K;

    float c[2][8][4];
#pragma unroll
    for (int i = 0; i < 2; i++)
#pragma unroll
        for (int j = 0; j < 8; j++)
#pragma unroll
            for (int q = 0; q < 4; q++) c[i][j][q] = 0.f;

    const int sub = lane >> 3;
    const int r8  = lane & 7;
    const uint32_t aoff = (uint32_t)((wm * 32 + (sub & 1) * 8 + r8) * GP + (sub >> 1) * 4) * 4;
    const uint32_t boff = BOFF + (uint32_t)((wn * 64 + (sub >> 1) * 8 + r8) * GP + (sub & 1) * 4) * 4;

    g2s_stage(Ab, Bb, K, sbase, tid);                   CPA_COMMIT();
    g2s_stage(Ab + 32, Bb + 32, K, sbase + STG_B, tid); CPA_COMMIT();

    for (int i = 0; i < iters; i++) {
        CPA_WAIT1();
        __syncthreads();
        if (i + 2 < iters) {
            uint32_t stg = sbase + (uint32_t)((i + 2) % 3) * STG_B;
            g2s_stage(Ab + (i + 2) * 32, Bb + (i + 2) * 32, K, stg, tid);
            CPA_COMMIT();
        }
        const uint32_t ab = sbase + (uint32_t)(i % 3) * STG_B + aoff;
        const uint32_t bb = sbase + (uint32_t)(i % 3) * STG_B + boff;

#pragma unroll
        for (int kk = 0; kk < 4; kk++) {
            uint32_t a[2][4], bf[4][4];
#pragma unroll
            for (int im = 0; im < 2; im++)
                LDSM4(a[im], ab + (uint32_t)(im * 16 * GP) * 4 + kk * 32);
#pragma unroll
            for (int nt = 0; nt < 4; nt++)
                LDSM4(bf[nt], bb + (uint32_t)(nt * 16 * GP) * 4 + kk * 32);
#pragma unroll
            for (int im = 0; im < 2; im++)
#pragma unroll
                for (int jn = 0; jn < 8; jn++)
                    MMA_TF32(c[im][jn], a[im],
                             bf[jn >> 1][(jn & 1) * 2],
                             bf[jn >> 1][(jn & 1) * 2 + 1]);
        }
    }

    const int g = lane >> 2, q = lane & 3;
#pragma unroll
    for (int im = 0; im < 2; im++)
#pragma unroll
        for (int jn = 0; jn < 8; jn++) {
            int row = m0 + wm * 32 + im * 16 + g;
            int col = n0 + wn * 64 + jn * 8 + q * 2;
            *(float2*)&C[(size_t)row * N + col]       = make_float2(c[im][jn][0], c[im][jn][1]);
            *(float2*)&C[(size_t)(row + 8) * N + col] = make_float2(c[im][jn][2], c[im][jn][3]);
        }
}

// ---------------- tf32 round-to-nearest copy -------------------------------
__global__ void round_tf32_k(const float4* __restrict__ in, float4* __restrict__ out, int n4) {
    int i = blockIdx.x * blockDim.x + threadIdx.x;
    if (i >= n4) return;
    out[i] = round4(in[i]);
}

// ---------------- RoPE for Q,K → [b,h,s,d] ---------------------------------
__global__ void rope_qk(const float* __restrict__ qkv,
                        float* __restrict__ Q, float* __restrict__ K) {
    int idx = blockIdx.x * blockDim.x + threadIdx.x;
    int d  = idx & 127;
    int s  = (idx >> 7) & 2047;
    int bh = idx >> 18;
    int i  = d & 63;
    float theta = (float)s * exp2f(-0.20762050593045998f * (float)i);
    float sn, cs;
    sincosf(theta, &sn, &cs);
    const float* row = qkv + (size_t)((bh >> 4) * 2048 + s) * QKV_N;
    int nq = (bh & 15) * 128;
    float qv = row[nq + d];
    float qp = row[nq + (d ^ 64)];
    float kv = row[2048 + nq + d];
    float kp = row[2048 + nq + (d ^ 64)];
    float qr = (d < 64) ? -qp : qp;
    float kr = (d < 64) ? -kp : kp;
    Q[idx] = qv * cs + qr * sn;
    K[idx] = kv * cs + kr * sn;
}

// ---------------- V transpose → [b,h,d,s] ----------------------------------
__global__ void transpose_v(const float* __restrict__ qkv, float* __restrict__ Vt) {
    __shared__ float t[32][33];
    int bh = blockIdx.z;
    int b = bh >> 4, h = bh & 15;
    int s0 = blockIdx.x * 32, d0 = blockIdx.y * 32;
    int tx = threadIdx.x, ty = threadIdx.y;
    const float* src = qkv + ((size_t)(b * SS + s0 + ty)) * QKV_N + 4096 + h * 128 + d0 + tx;
#pragma unroll
    for (int j = 0; j < 32; j += 8)
        t[ty + j][tx] = src[(size_t)j * QKV_N];
    __syncthreads();
    float* dst = Vt + ((size_t)bh * DD + d0 + ty) * SS + s0 + tx;
#pragma unroll
    for (int j = 0; j < 32; j += 8)
        dst[(size_t)j * SS] = t[tx][ty + j];
}

// ---------------- Flash attention via mma.sync tf32 ------------------------
#define QP 132                               // pitch (floats) for Qs/Ks
#define PP 68                                // pitch for Vs/Ps
#define ATTN2_SMEM ((128 * QP + 64 * QP + 128 * PP + 128 * PP) * 4)

__global__ __launch_bounds__(256, 1)
void attn_mma(const float* __restrict__ Qg_, const float* __restrict__ Kg_,
              const float* __restrict__ Vt_, float* __restrict__ Y) {
    extern __shared__ float sm[];
    float* Qs = sm;                          // [128][QP]  rows=qrow cols=d
    float* Ks = Qs + 128 * QP;               // [64][QP]   rows=kcol cols=d
    float* Vs = Ks + 64 * QP;                // [128][PP]  rows=d    cols=kcol
    float* Ps = Vs + 128 * PP;               // [128][PP]  rows=qrow cols=kcol

    const int tid  = threadIdx.x;
    const int wid  = tid >> 5;
    const int lane = tid & 31;
    const int qb = gridDim.x - 1 - blockIdx.x;
    const int h  = blockIdx.y;
    const int b  = blockIdx.z;
    const int q0 = qb * 128;

    const size_t bh = (size_t)(b * HH + h);
    const float* Qg = Qg_ + bh * SS * DD;
    const float* Kg = Kg_ + bh * SS * DD;
    const float* Vg = Vt_ + bh * DD * SS;

    const float scale = 0.088388347648318447f;
#pragma unroll
    for (int p = 0; p < 16; p++) {
        int idx = tid + p * 256;
        int row = idx >> 5, ch = idx & 31;
        float4 v = *(const float4*)&Qg[(size_t)(q0 + row) * DD + ch * 4];
        v.x *= scale; v.y *= scale; v.z *= scale; v.w *= scale;
        *(float4*)&Qs[row * QP + ch * 4] = round4(v);
    }

    const int sub = lane >> 3, r8 = lane & 7;
    const int g = lane >> 2, qq = lane & 3;
    const uint32_t a_q = smem_u32(Qs) + (uint32_t)((wid * 16 + (sub & 1) * 8 + r8) * QP + (sub >> 1) * 4) * 4;
    const uint32_t b_k = smem_u32(Ks) + (uint32_t)(((sub >> 1) * 8 + r8) * QP + (sub & 1) * 4) * 4;
    const uint32_t a_p = smem_u32(Ps) + (uint32_t)((wid * 16 + (sub & 1) * 8 + r8) * PP + (sub >> 1) * 4) * 4;
    const uint32_t b_v = smem_u32(Vs) + (uint32_t)(((sub >> 1) * 8 + r8) * PP + (sub & 1) * 4) * 4;

    float o[16][4];
#pragma unroll
    for (int i = 0; i < 16; i++)
#pragma unroll
        for (int j = 0; j < 4; j++) o[i][j] = 0.f;
    float m0v = -1e30f, m1v = -1e30f, l0 = 0.f, l1 = 0.f;

    const int nkt = 2 * qb + 2;
    for (int kt = 0; kt < nkt; kt++) {
        const int k0 = kt * 64;
        __syncthreads();
#pragma unroll
        for (int p = 0; p < 8; p++) {
            int idx = tid + p * 256;
            int row = idx >> 5, ch = idx & 31;
            *(float4*)&Ks[row * QP + ch * 4] =
                round4(*(const float4*)&Kg[(size_t)(k0 + row) * DD + ch * 4]);
        }
#pragma unroll
        for (int p = 0; p < 8; p++) {
            int idx = tid + p * 256;
            int row = idx >> 4, ch = idx & 15;
            *(float4*)&Vs[row * PP + ch * 4] =
                round4(*(const float4*)&Vg[(size_t)row * SS + k0 + ch * 4]);
        }
        __syncthreads();

        float s[8][4];
#pragma unroll
        for (int i = 0; i < 8; i++)
#pragma unroll
            for (int j = 0; j < 4; j++) s[i][j] = 0.f;
#pragma unroll
        for (int kd = 0; kd < 16; kd++) {
            uint32_t a[4];
            LDSM4(a, a_q + kd * 32);
            uint32_t bf[4][4];
#pragma unroll
            for (int nt = 0; nt < 4; nt++)
                LDSM4(bf[nt], b_k + (uint32_t)(nt * 16 * QP) * 4 + kd * 32);
#pragma unroll
            for (int nt = 0; nt < 4; nt++) {
                MMA_TF32(s[nt * 2],     a, bf[nt][0], bf[nt][1]);
                MMA_TF32(s[nt * 2 + 1], a, bf[nt][2], bf[nt][3]);
            }
        }

        if (kt >= 2 * qb) {
            int row0 = q0 + wid * 16 + g;
#pragma unroll
            for (int j = 0; j < 8; j++) {
                int c = k0 + j * 8 + qq * 2;
                if (c     > row0)     s[j][0] = -1e30f;
                if (c + 1 > row0)     s[j][1] = -1e30f;
                if (c     > row0 + 8) s[j][2] = -1e30f;
                if (c + 1 > row0 + 8) s[j][3] = -1e30f;
            }
        }

        float tm0 = -1e30f, tm1 = -1e30f;
#pragma unroll
        for (int j = 0; j < 8; j++) {
            tm0 = fmaxf(tm0, fmaxf(s[j][0], s[j][1]));
            tm1 = fmaxf(tm1, fmaxf(s[j][2], s[j][3]));
        }
        tm0 = fmaxf(tm0, __shfl_xor_sync(0xffffffffu, tm0, 1));
        tm0 = fmaxf(tm0, __shfl_xor_sync(0xffffffffu, tm0, 2));
        tm1 = fmaxf(tm1, __shfl_xor_sync(0xffffffffu, tm1, 1));
        tm1 = fmaxf(tm1, __shfl_xor_sync(0xffffffffu, tm1, 2));
        float mn0 = fmaxf(m0v, tm0), mn1 = fmaxf(m1v, tm1);
        float al0 = __expf(m0v - mn0), al1 = __expf(m1v - mn1);
        m0v = mn0; m1v = mn1;
        float rs0 = 0.f, rs1 = 0.f;
#pragma unroll
        for (int j = 0; j < 8; j++) {
            s[j][0] = __expf(s[j][0] - mn0);
            s[j][1] = __expf(s[j][1] - mn0);
            s[j][2] = __expf(s[j][2] - mn1);
            s[j][3] = __expf(s[j][3] - mn1);
            rs0 += s[j][0] + s[j][1];
            rs1 += s[j][2] + s[j][3];
        }
        rs0 += __shfl_xor_sync(0xffffffffu, rs0, 1);
        rs0 += __shfl_xor_sync(0xffffffffu, rs0, 2);
        rs1 += __shfl_xor_sync(0xffffffffu, rs1, 1);
        rs1 += __shfl_xor_sync(0xffffffffu, rs1, 2);
        l0 = l0 * al0 + rs0;
        l1 = l1 * al1 + rs1;
#pragma unroll
        for (int nt = 0; nt < 16; nt++) {
            o[nt][0] *= al0; o[nt][1] *= al0;
            o[nt][2] *= al1; o[nt][3] *= al1;
        }

        {
            int pr0 = (wid * 16 + g) * PP;
#pragma unroll
            for (int j = 0; j < 8; j++) {
                *(float2*)&Ps[pr0 + j * 8 + qq * 2] =
                    make_float2(to_tf32(s[j][0]), to_tf32(s[j][1]));
                *(float2*)&Ps[pr0 + 8 * PP + j * 8 + qq * 2] =
                    make_float2(to_tf32(s[j][2]), to_tf32(s[j][3]));
            }
        }
        __syncwarp();

#pragma unroll
        for (int jk = 0; jk < 8; jk++) {
            uint32_t a[4];
            LDSM4(a, a_p + jk * 32);
#pragma unroll
            for (int nt = 0; nt < 8; nt++) {
                uint32_t bf[4];
                LDSM4(bf, b_v + (uint32_t)(nt * 16 * PP) * 4 + jk * 32);
                MMA_TF32(o[nt * 2],     a, bf[0], bf[1]);
                MMA_TF32(o[nt * 2 + 1], a, bf[2], bf[3]);
            }
        }
    }

    float i0 = 1.f / l0, i1 = 1.f / l1;
    int row0 = q0 + wid * 16 + g;
    size_t base0 = ((size_t)b * SS + row0) * EE + h * 128;
    size_t base1 = base0 + (size_t)8 * EE;
#pragma unroll
    for (int nt = 0; nt < 16; nt++) {
        int col = nt * 8 + qq * 2;
        *(float2*)&Y[base0 + col] =
            make_float2(to_tf32(o[nt][0] * i0), to_tf32(o[nt][1] * i0));
        *(float2*)&Y[base1 + col] =
            make_float2(to_tf32(o[nt][2] * i1), to_tf32(o[nt][3] * i1));
    }
}

// ---------------- launch -----------------------------------------------------
extern "C" void kernel_launch(void* const* d_in, const int* in_sizes, int n_in,
                              void* d_out, int out_size) {
    const float* x     = (const float*)d_in[0];
    const float* w_qkv = (const float*)d_in[1];
    const float* w_out = (const float*)d_in[2];
    float* out = (float*)d_out;

    float *p_x, *p_wqkv, *p_wout, *p_qkv, *p_Q, *p_K, *p_Vt, *p_y;
    cudaGetSymbolAddress((void**)&p_x,    g_x);
    cudaGetSymbolAddress((void**)&p_wqkv, g_wqkv);
    cudaGetSymbolAddress((void**)&p_wout, g_wout);
    cudaGetSymbolAddress((void**)&p_qkv,  g_qkv);
    cudaGetSymbolAddress((void**)&p_Q,    g_Q);
    cudaGetSymbolAddress((void**)&p_K,    g_K);
    cudaGetSymbolAddress((void**)&p_Vt,   g_Vt);
    cudaGetSymbolAddress((void**)&p_y,    g_y);

    cudaFuncSetAttribute(gemm_mma, cudaFuncAttributeMaxDynamicSharedMemorySize, GEMM_SMEM);
    cudaFuncSetAttribute(attn_mma, cudaFuncAttributeMaxDynamicSharedMemorySize, ATTN2_SMEM);

    // 0) round GEMM operands to tf32 (RNA)
    round_tf32_k<<<(MROWS * EE / 4 + 255) / 256, 256>>>((const float4*)x, (float4*)p_x, MROWS * EE / 4);
    round_tf32_k<<<(QKV_N * EE / 4 + 255) / 256, 256>>>((const float4*)w_qkv, (float4*)p_wqkv, QKV_N * EE / 4);
    round_tf32_k<<<(EE * EE / 4 + 255) / 256, 256>>>((const float4*)w_out, (float4*)p_wout, EE * EE / 4);

    // 1) qkv = x @ w_qkv^T
    gemm_mma<<<dim3(QKV_N / 256, MROWS / 128), 512, GEMM_SMEM>>>(p_x, p_wqkv, p_qkv, QKV_N, EE);
    // 2) RoPE → Q,K [b,h,s,d]; V transpose → [b,h,d,s]
    rope_qk<<<(BB * HH * SS * DD) / 256, 256>>>(p_qkv, p_Q, p_K);
    transpose_v<<<dim3(SS / 32, DD / 32, BB * HH), dim3(32, 8)>>>(p_qkv, p_Vt);
    // 3) flash attention (mma.sync tf32)
    attn_mma<<<dim3(SS / 128, HH, BB), 256, ATTN2_SMEM>>>(p_Q, p_K, p_Vt, p_y);
    // 4) out = y @ w_out^T
    gemm_mma<<<dim3(EE / 256, MROWS / 128), 512, GEMM_SMEM>>>(p_y, p_wout, out, EE, EE);
}

// round 7
// speedup vs baseline: 3.8175x; 1.0513x over previous
#include <cuda_runtime.h>
#include <cuda_bf16.h>
#include <cstdint>
#include <math.h>

// Problem constants
#define BB 2
#define SS 2048
#define EE 2048
#define HH 16
#define DD 128
#define MROWS (BB * SS)          // 4096
#define QKV_N (3 * EE)           // 6144

// ---------------- scratch (device globals: allocation-free) ----------------
__device__ float g_x   [(size_t)MROWS * EE];            // tf32-rounded x
__device__ float g_wqkv[(size_t)QKV_N * EE];            // tf32-rounded w_qkv
__device__ float g_wout[(size_t)EE * EE];               // tf32-rounded w_out
__device__ float g_qkv [(size_t)MROWS * QKV_N];         // [4096, 6144] fp32
__device__ float g_Q   [(size_t)BB * HH * SS * DD];     // [b,h,s,d] (roped)
__device__ float g_K   [(size_t)BB * HH * SS * DD];     // [b,h,s,d] (roped)
__device__ float g_Vt  [(size_t)BB * HH * DD * SS];     // [b,h,d,s]
__device__ float g_y   [(size_t)MROWS * EE];            // [b,s,h,d], tf32-rounded

// ======================= helpers ===========================================
__device__ __forceinline__ uint32_t smem_u32(const void* p) {
    uint32_t a;
    asm("{ .reg .u64 t; cvta.to.shared.u64 t, %1; cvt.u32.u64 %0, t; }"
        : "=r"(a) : "l"(p));
    return a;
}

__device__ __forceinline__ float to_tf32(float x) {
    uint32_t u;
    asm("cvt.rna.tf32.f32 %0, %1;" : "=r"(u) : "f"(x));
    return __uint_as_float(u);
}

__device__ __forceinline__ float4 round4(float4 v) {
    v.x = to_tf32(v.x); v.y = to_tf32(v.y);
    v.z = to_tf32(v.z); v.w = to_tf32(v.w);
    return v;
}

#define CPA16(dst, src) \
    asm volatile("cp.async.cg.shared.global [%0], [%1], 16;" :: "r"(dst), "l"(src))
#define CPA_COMMIT()  asm volatile("cp.async.commit_group;" ::: "memory")
#define CPA_WAIT1()   asm volatile("cp.async.wait_group 1;" ::: "memory")

#define LDSM4(r, addr)                                                        \
    asm volatile("ldmatrix.sync.aligned.m8n8.x4.shared.b16 {%0,%1,%2,%3}, [%4];" \
        : "=r"((r)[0]), "=r"((r)[1]), "=r"((r)[2]), "=r"((r)[3]) : "r"(addr))

#define MMA_TF32(c, a, b0, b1)                                                \
    asm volatile("mma.sync.aligned.m16n8k8.row.col.f32.tf32.tf32.f32 "        \
        "{%0,%1,%2,%3}, {%4,%5,%6,%7}, {%8,%9}, {%0,%1,%2,%3};"               \
        : "+f"((c)[0]), "+f"((c)[1]), "+f"((c)[2]), "+f"((c)[3])              \
        : "r"((a)[0]), "r"((a)[1]), "r"((a)[2]), "r"((a)[3]), "r"(b0), "r"(b1))

// ============ mma.sync tf32 GEMM: C[M,N] = A[M,K] @ B[N,K]^T ===============
// CTA 128x128, 256 thr / 8 warps (4m x 2n), warptile 32x64, 3-stage cp.async
// 2 CTAs per SM (110.6 KB SMEM each) to overlap barrier/wait phases.
#define GP 36                                // SMEM pitch (floats), %32==4
#define BOFF (128 * GP * 4)                  // B offset within stage (bytes)
#define STG_B ((128 + 128) * GP * 4)         // 36864 bytes
#define GEMM_SMEM (3 * STG_B)                // 110592 bytes

__device__ __forceinline__ void g2s_stage(const float* A, const float* B, int K,
                                          uint32_t stg, int tid) {
#pragma unroll
    for (int j = 0; j < 4; j++) {            // A: 128 rows x 8 chunks
        int cid = tid + j * 256;
        int row = cid >> 3, chk = cid & 7;
        CPA16(stg + (uint32_t)(row * GP + chk * 4) * 4,
              A + (size_t)row * K + chk * 4);
    }
#pragma unroll
    for (int j = 0; j < 4; j++) {            // B: 128 rows x 8 chunks
        int cid = tid + j * 256;
        int row = cid >> 3, chk = cid & 7;
        CPA16(stg + BOFF + (uint32_t)(row * GP + chk * 4) * 4,
              B + (size_t)row * K + chk * 4);
    }
}

__global__ __launch_bounds__(256, 2)
void gemm_mma(const float* __restrict__ A, const float* __restrict__ B,
              float* __restrict__ C, int N, int K) {
    extern __shared__ char smem[];
    const uint32_t sbase = smem_u32(smem);
    const int tid  = threadIdx.x;
    const int wid  = tid >> 5;
    const int lane = tid & 31;
    const int wm   = wid >> 1;               // 0..3 (32 rows)
    const int wn   = wid & 1;                // 0..1 (64 cols)
    const int m0 = blockIdx.y * 128;
    const int n0 = blockIdx.x * 128;
    const int iters = K >> 5;

    const float* Ab = A + (size_t)m0 * K;
    const float* Bb = B + (size_t)n0 * K;

    float c[2][8][4];
#pragma unroll
    for (int i = 0; i < 2; i++)
#pragma unroll
        for (int j = 0; j < 8; j++)
#pragma unroll
            for (int q = 0; q < 4; q++) c[i][j][q] = 0.f;

    const int sub = lane >> 3;
    const int r8  = lane & 7;
    const uint32_t aoff = (uint32_t)((wm * 32 + (sub & 1) * 8 + r8) * GP + (sub >> 1) * 4) * 4;
    const uint32_t boff = BOFF + (uint32_t)((wn * 64 + (sub >> 1) * 8 + r8) * GP + (sub & 1) * 4) * 4;

    g2s_stage(Ab, Bb, K, sbase, tid);                   CPA_COMMIT();
    g2s_stage(Ab + 32, Bb + 32, K, sbase + STG_B, tid); CPA_COMMIT();

    for (int i = 0; i < iters; i++) {
        CPA_WAIT1();
        __syncthreads();
        if (i + 2 < iters) {
            uint32_t stg = sbase + (uint32_t)((i + 2) % 3) * STG_B;
            g2s_stage(Ab + (i + 2) * 32, Bb + (i + 2) * 32, K, stg, tid);
            CPA_COMMIT();
        }
        const uint32_t ab = sbase + (uint32_t)(i % 3) * STG_B + aoff;
        const uint32_t bb = sbase + (uint32_t)(i % 3) * STG_B + boff;

#pragma unroll
        for (int kk = 0; kk < 4; kk++) {
            uint32_t a[2][4], bf[4][4];
#pragma unroll
            for (int im = 0; im < 2; im++)
                LDSM4(a[im], ab + (uint32_t)(im * 16 * GP) * 4 + kk * 32);
#pragma unroll
            for (int nt = 0; nt < 4; nt++)
                LDSM4(bf[nt], bb + (uint32_t)(nt * 16 * GP) * 4 + kk * 32);
#pragma unroll
            for (int im = 0; im < 2; im++)
#pragma unroll
                for (int jn = 0; jn < 8; jn++)
                    MMA_TF32(c[im][jn], a[im],
                             bf[jn >> 1][(jn & 1) * 2],
                             bf[jn >> 1][(jn & 1) * 2 + 1]);
        }
    }

    const int g = lane >> 2, q = lane & 3;
#pragma unroll
    for (int im = 0; im < 2; im++)
#pragma unroll
        for (int jn = 0; jn < 8; jn++) {
            int row = m0 + wm * 32 + im * 16 + g;
            int col = n0 + wn * 64 + jn * 8 + q * 2;
            *(float2*)&C[(size_t)row * N + col]       = make_float2(c[im][jn][0], c[im][jn][1]);
            *(float2*)&C[(size_t)(row + 8) * N + col] = make_float2(c[im][jn][2], c[im][jn][3]);
        }
}

// ---------------- tf32 round-to-nearest copy -------------------------------
__global__ void round_tf32_k(const float4* __restrict__ in, float4* __restrict__ out, int n4) {
    int i = blockIdx.x * blockDim.x + threadIdx.x;
    if (i >= n4) return;
    out[i] = round4(in[i]);
}

// ---------------- RoPE for Q,K → [b,h,s,d] ---------------------------------
__global__ void rope_qk(const float* __restrict__ qkv,
                        float* __restrict__ Q, float* __restrict__ K) {
    int idx = blockIdx.x * blockDim.x + threadIdx.x;
    int d  = idx & 127;
    int s  = (idx >> 7) & 2047;
    int bh = idx >> 18;
    int i  = d & 63;
    float theta = (float)s * exp2f(-0.20762050593045998f * (float)i);
    float sn, cs;
    sincosf(theta, &sn, &cs);
    const float* row = qkv + (size_t)((bh >> 4) * 2048 + s) * QKV_N;
    int nq = (bh & 15) * 128;
    float qv = row[nq + d];
    float qp = row[nq + (d ^ 64)];
    float kv = row[2048 + nq + d];
    float kp = row[2048 + nq + (d ^ 64)];
    float qr = (d < 64) ? -qp : qp;
    float kr = (d < 64) ? -kp : kp;
    Q[idx] = qv * cs + qr * sn;
    K[idx] = kv * cs + kr * sn;
}

// ---------------- V transpose → [b,h,d,s] ----------------------------------
__global__ void transpose_v(const float* __restrict__ qkv, float* __restrict__ Vt) {
    __shared__ float t[32][33];
    int bh = blockIdx.z;
    int b = bh >> 4, h = bh & 15;
    int s0 = blockIdx.x * 32, d0 = blockIdx.y * 32;
    int tx = threadIdx.x, ty = threadIdx.y;
    const float* src = qkv + ((size_t)(b * SS + s0 + ty)) * QKV_N + 4096 + h * 128 + d0 + tx;
#pragma unroll
    for (int j = 0; j < 32; j += 8)
        t[ty + j][tx] = src[(size_t)j * QKV_N];
    __syncthreads();
    float* dst = Vt + ((size_t)bh * DD + d0 + ty) * SS + s0 + tx;
#pragma unroll
    for (int j = 0; j < 32; j += 8)
        dst[(size_t)j * SS] = t[tx][ty + j];
}

// ---------------- Flash attention via mma.sync tf32 ------------------------
#define QP 132                               // pitch (floats) for Qs/Ks
#define PP 68                                // pitch for Vs/Ps
#define ATTN2_SMEM ((128 * QP + 64 * QP + 128 * PP + 128 * PP) * 4)

__global__ __launch_bounds__(256, 1)
void attn_mma(const float* __restrict__ Qg_, const float* __restrict__ Kg_,
              const float* __restrict__ Vt_, float* __restrict__ Y) {
    extern __shared__ float sm[];
    float* Qs = sm;                          // [128][QP]  rows=qrow cols=d
    float* Ks = Qs + 128 * QP;               // [64][QP]   rows=kcol cols=d
    float* Vs = Ks + 64 * QP;                // [128][PP]  rows=d    cols=kcol
    float* Ps = Vs + 128 * PP;               // [128][PP]  rows=qrow cols=kcol

    const int tid  = threadIdx.x;
    const int wid  = tid >> 5;
    const int lane = tid & 31;
    const int qb = gridDim.x - 1 - blockIdx.x;
    const int h  = blockIdx.y;
    const int b  = blockIdx.z;
    const int q0 = qb * 128;

    const size_t bh = (size_t)(b * HH + h);
    const float* Qg = Qg_ + bh * SS * DD;
    const float* Kg = Kg_ + bh * SS * DD;
    const float* Vg = Vt_ + bh * DD * SS;

    const float scale = 0.088388347648318447f;
#pragma unroll
    for (int p = 0; p < 16; p++) {
        int idx = tid + p * 256;
        int row = idx >> 5, ch = idx & 31;
        float4 v = *(const float4*)&Qg[(size_t)(q0 + row) * DD + ch * 4];
        v.x *= scale; v.y *= scale; v.z *= scale; v.w *= scale;
        *(float4*)&Qs[row * QP + ch * 4] = round4(v);
    }

    const int sub = lane >> 3, r8 = lane & 7;
    const int g = lane >> 2, qq = lane & 3;
    const uint32_t a_q = smem_u32(Qs) + (uint32_t)((wid * 16 + (sub & 1) * 8 + r8) * QP + (sub >> 1) * 4) * 4;
    const uint32_t b_k = smem_u32(Ks) + (uint32_t)(((sub >> 1) * 8 + r8) * QP + (sub & 1) * 4) * 4;
    const uint32_t a_p = smem_u32(Ps) + (uint32_t)((wid * 16 + (sub & 1) * 8 + r8) * PP + (sub >> 1) * 4) * 4;
    const uint32_t b_v = smem_u32(Vs) + (uint32_t)(((sub >> 1) * 8 + r8) * PP + (sub & 1) * 4) * 4;

    float o[16][4];
#pragma unroll
    for (int i = 0; i < 16; i++)
#pragma unroll
        for (int j = 0; j < 4; j++) o[i][j] = 0.f;
    float m0v = -1e30f, m1v = -1e30f, l0 = 0.f, l1 = 0.f;

    const int nkt = 2 * qb + 2;
    for (int kt = 0; kt < nkt; kt++) {
        const int k0 = kt * 64;
        __syncthreads();
#pragma unroll
        for (int p = 0; p < 8; p++) {
            int idx = tid + p * 256;
            int row = idx >> 5, ch = idx & 31;
            *(float4*)&Ks[row * QP + ch * 4] =
                round4(*(const float4*)&Kg[(size_t)(k0 + row) * DD + ch * 4]);
        }
#pragma unroll
        for (int p = 0; p < 8; p++) {
            int idx = tid + p * 256;
            int row = idx >> 4, ch = idx & 15;
            *(float4*)&Vs[row * PP + ch * 4] =
                round4(*(const float4*)&Vg[(size_t)row * SS + k0 + ch * 4]);
        }
        __syncthreads();

        float s[8][4];
#pragma unroll
        for (int i = 0; i < 8; i++)
#pragma unroll
            for (int j = 0; j < 4; j++) s[i][j] = 0.f;
#pragma unroll
        for (int kd = 0; kd < 16; kd++) {
            uint32_t a[4];
            LDSM4(a, a_q + kd * 32);
            uint32_t bf[4][4];
#pragma unroll
            for (int nt = 0; nt < 4; nt++)
                LDSM4(bf[nt], b_k + (uint32_t)(nt * 16 * QP) * 4 + kd * 32);
#pragma unroll
            for (int nt = 0; nt < 4; nt++) {
                MMA_TF32(s[nt * 2],     a, bf[nt][0], bf[nt][1]);
                MMA_TF32(s[nt * 2 + 1], a, bf[nt][2], bf[nt][3]);
            }
        }

        if (kt >= 2 * qb) {
            int row0 = q0 + wid * 16 + g;
#pragma unroll
            for (int j = 0; j < 8; j++) {
                int c = k0 + j * 8 + qq * 2;
                if (c     > row0)     s[j][0] = -1e30f;
                if (c + 1 > row0)     s[j][1] = -1e30f;
                if (c     > row0 + 8) s[j][2] = -1e30f;
                if (c + 1 > row0 + 8) s[j][3] = -1e30f;
            }
        }

        float tm0 = -1e30f, tm1 = -1e30f;
#pragma unroll
        for (int j = 0; j < 8; j++) {
            tm0 = fmaxf(tm0, fmaxf(s[j][0], s[j][1]));
            tm1 = fmaxf(tm1, fmaxf(s[j][2], s[j][3]));
        }
        tm0 = fmaxf(tm0, __shfl_xor_sync(0xffffffffu, tm0, 1));
        tm0 = fmaxf(tm0, __shfl_xor_sync(0xffffffffu, tm0, 2));
        tm1 = fmaxf(tm1, __shfl_xor_sync(0xffffffffu, tm1, 1));
        tm1 = fmaxf(tm1, __shfl_xor_sync(0xffffffffu, tm1, 2));
        float mn0 = fmaxf(m0v, tm0), mn1 = fmaxf(m1v, tm1);
        float al0 = __expf(m0v - mn0), al1 = __expf(m1v - mn1);
        m0v = mn0; m1v = mn1;
        float rs0 = 0.f, rs1 = 0.f;
#pragma unroll
        for (int j = 0; j < 8; j++) {
            s[j][0] = __expf(s[j][0] - mn0);
            s[j][1] = __expf(s[j][1] - mn0);
            s[j][2] = __expf(s[j][2] - mn1);
            s[j][3] = __expf(s[j][3] - mn1);
            rs0 += s[j][0] + s[j][1];
            rs1 += s[j][2] + s[j][3];
        }
        rs0 += __shfl_xor_sync(0xffffffffu, rs0, 1);
        rs0 += __shfl_xor_sync(0xffffffffu, rs0, 2);
        rs1 += __shfl_xor_sync(0xffffffffu, rs1, 1);
        rs1 += __shfl_xor_sync(0xffffffffu, rs1, 2);
        l0 = l0 * al0 + rs0;
        l1 = l1 * al1 + rs1;
#pragma unroll
        for (int nt = 0; nt < 16; nt++) {
            o[nt][0] *= al0; o[nt][1] *= al0;
            o[nt][2] *= al1; o[nt][3] *= al1;
        }

        {
            int pr0 = (wid * 16 + g) * PP;
#pragma unroll
            for (int j = 0; j < 8; j++) {
                *(float2*)&Ps[pr0 + j * 8 + qq * 2] =
                    make_float2(to_tf32(s[j][0]), to_tf32(s[j][1]));
                *(float2*)&Ps[pr0 + 8 * PP + j * 8 + qq * 2] =
                    make_float2(to_tf32(s[j][2]), to_tf32(s[j][3]));
            }
        }
        __syncwarp();

#pragma unroll
        for (int jk = 0; jk < 8; jk++) {
            uint32_t a[4];
            LDSM4(a, a_p + jk * 32);
#pragma unroll
            for (int nt = 0; nt < 8; nt++) {
                uint32_t bf[4];
                LDSM4(bf, b_v + (uint32_t)(nt * 16 * PP) * 4 + jk * 32);
                MMA_TF32(o[nt * 2],     a, bf[0], bf[1]);
                MMA_TF32(o[nt * 2 + 1], a, bf[2], bf[3]);
            }
        }
    }

    float i0 = 1.f / l0, i1 = 1.f / l1;
    int row0 = q0 + wid * 16 + g;
    size_t base0 = ((size_t)b * SS + row0) * EE + h * 128;
    size_t base1 = base0 + (size_t)8 * EE;
#pragma unroll
    for (int nt = 0; nt < 16; nt++) {
        int col = nt * 8 + qq * 2;
        *(float2*)&Y[base0 + col] =
            make_float2(to_tf32(o[nt][0] * i0), to_tf32(o[nt][1] * i0));
        *(float2*)&Y[base1 + col] =
            make_float2(to_tf32(o[nt][2] * i1), to_tf32(o[nt][3] * i1));
    }
}

// ---------------- launch -----------------------------------------------------
extern "C" void kernel_launch(void* const* d_in, const int* in_sizes, int n_in,
                              void* d_out, int out_size) {
    const float* x     = (const float*)d_in[0];
    const float* w_qkv = (const float*)d_in[1];
    const float* w_out = (const float*)d_in[2];
    float* out = (float*)d_out;

    float *p_x, *p_wqkv, *p_wout, *p_qkv, *p_Q, *p_K, *p_Vt, *p_y;
    cudaGetSymbolAddress((void**)&p_x,    g_x);
    cudaGetSymbolAddress((void**)&p_wqkv, g_wqkv);
    cudaGetSymbolAddress((void**)&p_wout, g_wout);
    cudaGetSymbolAddress((void**)&p_qkv,  g_qkv);
    cudaGetSymbolAddress((void**)&p_Q,    g_Q);
    cudaGetSymbolAddress((void**)&p_K,    g_K);
    cudaGetSymbolAddress((void**)&p_Vt,   g_Vt);
    cudaGetSymbolAddress((void**)&p_y,    g_y);

    cudaFuncSetAttribute(gemm_mma, cudaFuncAttributeMaxDynamicSharedMemorySize, GEMM_SMEM);
    cudaFuncSetAttribute(attn_mma, cudaFuncAttributeMaxDynamicSharedMemorySize, ATTN2_SMEM);

    // 0) round GEMM operands to tf32 (RNA)
    round_tf32_k<<<(MROWS * EE / 4 + 255) / 256, 256>>>((const float4*)x, (float4*)p_x, MROWS * EE / 4);
    round_tf32_k<<<(QKV_N * EE / 4 + 255) / 256, 256>>>((const float4*)w_qkv, (float4*)p_wqkv, QKV_N * EE / 4);
    round_tf32_k<<<(EE * EE / 4 + 255) / 256, 256>>>((const float4*)w_out, (float4*)p_wout, EE * EE / 4);

    // 1) qkv = x @ w_qkv^T
    gemm_mma<<<dim3(QKV_N / 128, MROWS / 128), 256, GEMM_SMEM>>>(p_x, p_wqkv, p_qkv, QKV_N, EE);
    // 2) RoPE → Q,K [b,h,s,d]; V transpose → [b,h,d,s]
    rope_qk<<<(BB * HH * SS * DD) / 256, 256>>>(p_qkv, p_Q, p_K);
    transpose_v<<<dim3(SS / 32, DD / 32, BB * HH), dim3(32, 8)>>>(p_qkv, p_Vt);
    // 3) flash attention (mma.sync tf32)
    attn_mma<<<dim3(SS / 128, HH, BB), 256, ATTN2_SMEM>>>(p_Q, p_K, p_Vt, p_y);
    // 4) out = y @ w_out^T
    gemm_mma<<<dim3(EE / 128, MROWS / 128), 256, GEMM_SMEM>>>(p_y, p_wout, out, EE, EE);
}